// round 5
// baseline (speedup 1.0000x reference)
#include <cuda_runtime.h>
#include <cstdint>
#include <math.h>

// Problem constants
#define BB 4
#define TT 2048
#define CC 512
#define HH 8
#define HD 64
#define MM (BB*TT)          // 8192
#define BH (BB*HH)          // 32

// ---------------- device scratch ----------------
__device__ float g_qkv[MM * 3 * CC];
__device__ float g_q[BH * TT * HD];
__device__ float g_k[BH * TT * HD];
__device__ float g_v[BH * TT * HD];
__device__ float g_att[MM * CC];

// ---------------- tf32 helpers ----------------
__device__ __forceinline__ unsigned f2tf32(float x) {
    unsigned r;
    asm("cvt.rna.tf32.f32 %0, %1;" : "=r"(r) : "f"(x));
    return r;
}

__device__ __forceinline__ void mma_tf32(float& c0, float& c1, float& c2, float& c3,
                                         unsigned a0, unsigned a1, unsigned a2, unsigned a3,
                                         unsigned b0, unsigned b1) {
    asm volatile(
        "mma.sync.aligned.m16n8k8.row.col.f32.tf32.tf32.f32 "
        "{%0,%1,%2,%3}, {%4,%5,%6,%7}, {%8,%9}, {%0,%1,%2,%3};"
        : "+f"(c0), "+f"(c1), "+f"(c2), "+f"(c3)
        : "r"(a0), "r"(a1), "r"(a2), "r"(a3), "r"(b0), "r"(b1));
}

// =====================================================================
// TF32 tensor-core GEMM: C[M,N] = A[M,K] @ W[N,K]^T
// 128x128 block, 8 warps (warp tile 64x32), BK=16, DOUBLE-BUFFERED smem:
// prefetch next k-tile into registers during compute, single
// __syncthreads per iteration. Stride 136 keeps fragment LDS
// conflict-free ((8q+g) mod 32 covers all banks).
// =====================================================================
__global__ void __launch_bounds__(256, 2) gemm_tf32_nt(const float* __restrict__ A,
                                                       const float* __restrict__ W,
                                                       float* __restrict__ Cmat,
                                                       int M, int N, int K) {
    __shared__ unsigned As[2][16][136];
    __shared__ unsigned Ws[2][16][136];

    const int tid  = threadIdx.x;
    const int warp = tid >> 5;
    const int lane = tid & 31;
    const int g    = lane >> 2;       // 0..7
    const int q    = lane & 3;        // 0..3
    const int bm = blockIdx.y * 128;
    const int bn = blockIdx.x * 128;
    const int wm = (warp & 1) * 64;
    const int wn = (warp >> 1) * 32;

    const int lm = tid & 127;
    const int lk = (tid >> 7) * 8;    // 0 or 8

    const float* Ap = A + (size_t)(bm + lm) * K + lk;
    const float* Wp = W + (size_t)(bn + lm) * K + lk;

    float acc[4][4][4];
#pragma unroll
    for (int mi = 0; mi < 4; mi++)
#pragma unroll
        for (int ni = 0; ni < 4; ni++)
#pragma unroll
            for (int c = 0; c < 4; c++) acc[mi][ni][c] = 0.f;

    // ---- preload stage 0 ----
    {
        float4 a1 = *(const float4*)(Ap);
        float4 a2 = *(const float4*)(Ap + 4);
        float4 w1 = *(const float4*)(Wp);
        float4 w2 = *(const float4*)(Wp + 4);
        As[0][lk + 0][lm] = f2tf32(a1.x); As[0][lk + 1][lm] = f2tf32(a1.y);
        As[0][lk + 2][lm] = f2tf32(a1.z); As[0][lk + 3][lm] = f2tf32(a1.w);
        As[0][lk + 4][lm] = f2tf32(a2.x); As[0][lk + 5][lm] = f2tf32(a2.y);
        As[0][lk + 6][lm] = f2tf32(a2.z); As[0][lk + 7][lm] = f2tf32(a2.w);
        Ws[0][lk + 0][lm] = f2tf32(w1.x); Ws[0][lk + 1][lm] = f2tf32(w1.y);
        Ws[0][lk + 2][lm] = f2tf32(w1.z); Ws[0][lk + 3][lm] = f2tf32(w1.w);
        Ws[0][lk + 4][lm] = f2tf32(w2.x); Ws[0][lk + 5][lm] = f2tf32(w2.y);
        Ws[0][lk + 6][lm] = f2tf32(w2.z); Ws[0][lk + 7][lm] = f2tf32(w2.w);
    }
    __syncthreads();

    int buf = 0;
    for (int k0 = 0; k0 < K; k0 += 16) {
        const bool more = (k0 + 16) < K;
        float4 a1, a2, w1, w2;
        if (more) {                       // prefetch next tile
            a1 = *(const float4*)(Ap + k0 + 16);
            a2 = *(const float4*)(Ap + k0 + 20);
            w1 = *(const float4*)(Wp + k0 + 16);
            w2 = *(const float4*)(Wp + k0 + 20);
        }

        // ---- compute on stage `buf` ----
#pragma unroll
        for (int ks = 0; ks < 2; ks++) {
            const int kk = ks * 8;
            unsigned af[4][4];
#pragma unroll
            for (int mi = 0; mi < 4; mi++) {
                const int m = wm + mi * 16;
                af[mi][0] = As[buf][kk + q][m + g];
                af[mi][1] = As[buf][kk + q][m + g + 8];
                af[mi][2] = As[buf][kk + q + 4][m + g];
                af[mi][3] = As[buf][kk + q + 4][m + g + 8];
            }
            unsigned bf[4][2];
#pragma unroll
            for (int ni = 0; ni < 4; ni++) {
                const int n = wn + ni * 8;
                bf[ni][0] = Ws[buf][kk + q][n + g];
                bf[ni][1] = Ws[buf][kk + q + 4][n + g];
            }
#pragma unroll
            for (int mi = 0; mi < 4; mi++)
#pragma unroll
                for (int ni = 0; ni < 4; ni++)
                    mma_tf32(acc[mi][ni][0], acc[mi][ni][1], acc[mi][ni][2], acc[mi][ni][3],
                             af[mi][0], af[mi][1], af[mi][2], af[mi][3],
                             bf[ni][0], bf[ni][1]);
        }

        if (more) {                       // fill the other stage
            const int nb = buf ^ 1;
            As[nb][lk + 0][lm] = f2tf32(a1.x); As[nb][lk + 1][lm] = f2tf32(a1.y);
            As[nb][lk + 2][lm] = f2tf32(a1.z); As[nb][lk + 3][lm] = f2tf32(a1.w);
            As[nb][lk + 4][lm] = f2tf32(a2.x); As[nb][lk + 5][lm] = f2tf32(a2.y);
            As[nb][lk + 6][lm] = f2tf32(a2.z); As[nb][lk + 7][lm] = f2tf32(a2.w);
            Ws[nb][lk + 0][lm] = f2tf32(w1.x); Ws[nb][lk + 1][lm] = f2tf32(w1.y);
            Ws[nb][lk + 2][lm] = f2tf32(w1.z); Ws[nb][lk + 3][lm] = f2tf32(w1.w);
            Ws[nb][lk + 4][lm] = f2tf32(w2.x); Ws[nb][lk + 5][lm] = f2tf32(w2.y);
            Ws[nb][lk + 6][lm] = f2tf32(w2.z); Ws[nb][lk + 7][lm] = f2tf32(w2.w);
            __syncthreads();
            buf = nb;
        }
    }

    // epilogue
#pragma unroll
    for (int mi = 0; mi < 4; mi++) {
#pragma unroll
        for (int ni = 0; ni < 4; ni++) {
            const int m = bm + wm + mi * 16 + g;
            const int n = bn + wn + ni * 8 + 2 * q;
            *(float2*)&Cmat[(size_t)m * N + n] =
                make_float2(acc[mi][ni][0], acc[mi][ni][1]);
            *(float2*)&Cmat[(size_t)(m + 8) * N + n] =
                make_float2(acc[mi][ni][2], acc[mi][ni][3]);
        }
    }
}

// =====================================================================
// RoPE + split qkv[8192][1536] -> g_q/g_k/g_v in [bh][t][d] layout.
// =====================================================================
__global__ void __launch_bounds__(256) rope_split(const float* __restrict__ qkv,
                                                  const float* __restrict__ cosp,
                                                  const float* __restrict__ sinp,
                                                  float* __restrict__ q,
                                                  float* __restrict__ k,
                                                  float* __restrict__ v) {
    int idx = blockIdx.x * blockDim.x + threadIdx.x;   // 32*2048*32
    int d  = idx & 31;
    int t  = (idx >> 5) & (TT - 1);
    int bh = idx >> 16;
    int b = bh >> 3, h = bh & 7;

    size_t rowq = (size_t)(b * TT + t) * (3 * CC);
    int c = h * HD + d;
    float c1 = cosp[t * HD + d],      s1 = sinp[t * HD + d];
    float c2 = cosp[t * HD + d + 32], s2 = sinp[t * HD + d + 32];
    size_t dst = (size_t)(bh * TT + t) * HD + d;

    float x1 = qkv[rowq + c];
    float x2 = qkv[rowq + c + 32];
    q[dst]      = x1 * c1 - x2 * s1;
    q[dst + 32] = x2 * c2 + x1 * s2;

    x1 = qkv[rowq + CC + c];
    x2 = qkv[rowq + CC + c + 32];
    k[dst]      = x1 * c1 - x2 * s1;
    k[dst + 32] = x2 * c2 + x1 * s2;

    v[dst]      = qkv[rowq + 2 * CC + c];
    v[dst + 32] = qkv[rowq + 2 * CC + c + 32];
}

// =====================================================================
// Flash attention (causal) on tensor cores: mma.sync m16n8k8 tf32.
// =====================================================================
__global__ void __launch_bounds__(128) attn_tc(const float* __restrict__ Q,
                                               const float* __restrict__ K,
                                               const float* __restrict__ V,
                                               float* __restrict__ Oatt) {
    __shared__ unsigned Ks[64][76];   // stride 76: (12g+q)%32 all-distinct
    __shared__ unsigned Vs[64][72];   // stride 72: (8q+g)%32 all-distinct

    const int tid  = threadIdx.x;
    const int warp = tid >> 5;
    const int lane = tid & 31;
    const int g    = lane >> 2;
    const int q    = lane & 3;
    const int qt   = (int)gridDim.x - 1 - (int)blockIdx.x;  // big tiles first
    const int q0   = qt * 64;
    const int bh   = blockIdx.y;
    const int row0 = q0 + warp * 16 + g;
    const int row1 = row0 + 8;

    unsigned Qa[8][4];
    {
        const float* q0p = Q + ((size_t)bh * TT + row0) * HD;
        const float* q1p = Q + ((size_t)bh * TT + row1) * HD;
#pragma unroll
        for (int k = 0; k < 8; k++) {
            Qa[k][0] = f2tf32(0.125f * q0p[8 * k + q]);
            Qa[k][1] = f2tf32(0.125f * q1p[8 * k + q]);
            Qa[k][2] = f2tf32(0.125f * q0p[8 * k + q + 4]);
            Qa[k][3] = f2tf32(0.125f * q1p[8 * k + q + 4]);
        }
    }

    float Oac[8][4];
#pragma unroll
    for (int j = 0; j < 8; j++)
#pragma unroll
        for (int i = 0; i < 4; i++) Oac[j][i] = 0.f;
    float m0_ = -1e30f, m1_ = -1e30f, l0_ = 0.f, l1_ = 0.f;

    const int la = 4 * g + (q >> 1);
    const int lb = la + 2;
    const bool odd = (q & 1);

    const int nkt = qt + 1;
    for (int kt = 0; kt < nkt; kt++) {
        const int k0 = kt * 64;
        __syncthreads();
        {
            const float* kb = K + ((size_t)bh * TT + k0) * HD;
            const float* vb = V + ((size_t)bh * TT + k0) * HD;
#pragma unroll
            for (int i = 0; i < 8; i++) {
                int idx4 = tid + i * 128;
                int row = idx4 >> 4, col = (idx4 & 15) * 4;
                float4 a = *(const float4*)(kb + row * HD + col);
                float4 b = *(const float4*)(vb + row * HD + col);
                *(uint4*)&Ks[row][col] = make_uint4(f2tf32(a.x), f2tf32(a.y),
                                                    f2tf32(a.z), f2tf32(a.w));
                *(uint4*)&Vs[row][col] = make_uint4(f2tf32(b.x), f2tf32(b.y),
                                                    f2tf32(b.z), f2tf32(b.w));
            }
        }
        __syncthreads();

        float S[8][4];
#pragma unroll
        for (int j = 0; j < 8; j++)
#pragma unroll
            for (int i = 0; i < 4; i++) S[j][i] = 0.f;

#pragma unroll
        for (int k = 0; k < 8; k++) {
#pragma unroll
            for (int j = 0; j < 8; j++) {
                unsigned b0 = Ks[8 * j + g][8 * k + q];
                unsigned b1 = Ks[8 * j + g][8 * k + q + 4];
                mma_tf32(S[j][0], S[j][1], S[j][2], S[j][3],
                         Qa[k][0], Qa[k][1], Qa[k][2], Qa[k][3], b0, b1);
            }
        }

        if (kt == nkt - 1) {
#pragma unroll
            for (int j = 0; j < 8; j++) {
                int c = k0 + 8 * j + 2 * q;
                if (c     > row0) S[j][0] = -1e30f;
                if (c + 1 > row0) S[j][1] = -1e30f;
                if (c     > row1) S[j][2] = -1e30f;
                if (c + 1 > row1) S[j][3] = -1e30f;
            }
        }

        float tm0 = -1e30f, tm1 = -1e30f;
#pragma unroll
        for (int j = 0; j < 8; j++) {
            tm0 = fmaxf(tm0, fmaxf(S[j][0], S[j][1]));
            tm1 = fmaxf(tm1, fmaxf(S[j][2], S[j][3]));
        }
        tm0 = fmaxf(tm0, __shfl_xor_sync(0xffffffffu, tm0, 1));
        tm0 = fmaxf(tm0, __shfl_xor_sync(0xffffffffu, tm0, 2));
        tm1 = fmaxf(tm1, __shfl_xor_sync(0xffffffffu, tm1, 1));
        tm1 = fmaxf(tm1, __shfl_xor_sync(0xffffffffu, tm1, 2));

        float nm0 = fmaxf(m0_, tm0), nm1 = fmaxf(m1_, tm1);
        float r0 = __expf(m0_ - nm0), r1 = __expf(m1_ - nm1);
        m0_ = nm0; m1_ = nm1;

        float rs0 = 0.f, rs1 = 0.f;
#pragma unroll
        for (int j = 0; j < 8; j++) {
            S[j][0] = __expf(S[j][0] - nm0);
            S[j][1] = __expf(S[j][1] - nm0);
            S[j][2] = __expf(S[j][2] - nm1);
            S[j][3] = __expf(S[j][3] - nm1);
            rs0 += S[j][0] + S[j][1];
            rs1 += S[j][2] + S[j][3];
        }
        rs0 += __shfl_xor_sync(0xffffffffu, rs0, 1);
        rs0 += __shfl_xor_sync(0xffffffffu, rs0, 2);
        rs1 += __shfl_xor_sync(0xffffffffu, rs1, 1);
        rs1 += __shfl_xor_sync(0xffffffffu, rs1, 2);
        l0_ = l0_ * r0 + rs0;
        l1_ = l1_ * r1 + rs1;

#pragma unroll
        for (int j = 0; j < 8; j++) {
            Oac[j][0] *= r0; Oac[j][1] *= r0;
            Oac[j][2] *= r1; Oac[j][3] *= r1;
        }

#pragma unroll
        for (int k = 0; k < 8; k++) {
            float w00 = __shfl_sync(0xffffffffu, S[k][0], la);
            float w01 = __shfl_sync(0xffffffffu, S[k][1], la);
            float w10 = __shfl_sync(0xffffffffu, S[k][0], lb);
            float w11 = __shfl_sync(0xffffffffu, S[k][1], lb);
            unsigned a0 = f2tf32(odd ? w01 : w00);
            unsigned a2 = f2tf32(odd ? w11 : w10);
            float x00 = __shfl_sync(0xffffffffu, S[k][2], la);
            float x01 = __shfl_sync(0xffffffffu, S[k][3], la);
            float x10 = __shfl_sync(0xffffffffu, S[k][2], lb);
            float x11 = __shfl_sync(0xffffffffu, S[k][3], lb);
            unsigned a1 = f2tf32(odd ? x01 : x00);
            unsigned a3 = f2tf32(odd ? x11 : x10);
#pragma unroll
            for (int j = 0; j < 8; j++) {
                unsigned b0 = Vs[8 * k + q][8 * j + g];
                unsigned b1 = Vs[8 * k + q + 4][8 * j + g];
                mma_tf32(Oac[j][0], Oac[j][1], Oac[j][2], Oac[j][3],
                         a0, a1, a2, a3, b0, b1);
            }
        }
    }

    const int b = bh >> 3, h = bh & 7;
    float inv0 = 1.f / l0_, inv1 = 1.f / l1_;
    float* o0 = Oatt + ((size_t)(b * TT) + row0) * CC + h * HD;
    float* o1 = Oatt + ((size_t)(b * TT) + row1) * CC + h * HD;
#pragma unroll
    for (int j = 0; j < 8; j++) {
        float2 v0 = make_float2(Oac[j][0] * inv0, Oac[j][1] * inv0);
        float2 v1 = make_float2(Oac[j][2] * inv1, Oac[j][3] * inv1);
        *(float2*)&o0[8 * j + 2 * q] = v0;
        *(float2*)&o1[8 * j + 2 * q] = v1;
    }
}

// =====================================================================
extern "C" void kernel_launch(void* const* d_in, const int* in_sizes, int n_in,
                              void* d_out, int out_size) {
    const float* x    = (const float*)d_in[0];
    const float* cosp = (const float*)d_in[1];
    const float* sinp = (const float*)d_in[2];
    const float* Wqkv = (const float*)d_in[3];
    const float* Wout = (const float*)d_in[4];
    float* out = (float*)d_out;

    float *qkv, *q, *k, *v, *att;
    cudaGetSymbolAddress((void**)&qkv, g_qkv);
    cudaGetSymbolAddress((void**)&q,   g_q);
    cudaGetSymbolAddress((void**)&k,   g_k);
    cudaGetSymbolAddress((void**)&v,   g_v);
    cudaGetSymbolAddress((void**)&att, g_att);

    // 1) qkv = x @ Wqkv^T            (tf32 TC, double-buffered)
    gemm_tf32_nt<<<dim3((3 * CC) / 128, MM / 128), 256>>>(x, Wqkv, qkv, MM, 3 * CC, CC);
    // 2) RoPE + split into head-major q/k/v
    rope_split<<<(BH * TT * 32) / 256, 256>>>(qkv, cosp, sinp, q, k, v);
    // 3) causal flash attention on tensor cores
    attn_tc<<<dim3(TT / 64, BH), 128>>>(q, k, v, att);
    // 4) out = att @ Wout^T          (tf32 TC, double-buffered)
    gemm_tf32_nt<<<dim3(CC / 128, MM / 128), 256>>>(att, Wout, out, MM, CC, CC);
}

// round 6
// speedup vs baseline: 1.0753x; 1.0753x over previous
#include <cuda_runtime.h>
#include <cstdint>
#include <math.h>

// Problem constants
#define BB 4
#define TT 2048
#define CC 512
#define HH 8
#define HD 64
#define MM (BB*TT)          // 8192
#define BH (BB*HH)          // 32

// ---------------- device scratch ----------------
__device__ float g_qkv[MM * 3 * CC];
__device__ float g_q[BH * TT * HD];
__device__ float g_k[BH * TT * HD];
__device__ float g_v[BH * TT * HD];
__device__ float g_att[MM * CC];

// ---------------- tf32 helpers ----------------
__device__ __forceinline__ unsigned f2tf32(float x) {
    unsigned r;
    asm("cvt.rna.tf32.f32 %0, %1;" : "=r"(r) : "f"(x));
    return r;
}

__device__ __forceinline__ void mma_tf32(float& c0, float& c1, float& c2, float& c3,
                                         unsigned a0, unsigned a1, unsigned a2, unsigned a3,
                                         unsigned b0, unsigned b1) {
    asm volatile(
        "mma.sync.aligned.m16n8k8.row.col.f32.tf32.tf32.f32 "
        "{%0,%1,%2,%3}, {%4,%5,%6,%7}, {%8,%9}, {%0,%1,%2,%3};"
        : "+f"(c0), "+f"(c1), "+f"(c2), "+f"(c3)
        : "r"(a0), "r"(a1), "r"(a2), "r"(a3), "r"(b0), "r"(b1));
}

// =====================================================================
// TF32 tensor-core GEMM: C[M,N] = A[M,K] @ W[N,K]^T
// Block tile 128x256, 8 warps in 2(m) x 4(n), warp tile 64x64, BK=16,
// double-buffered. Bytes/MMA cut ~2x vs 128x128: smem reads 64KB +
// writes 24KB per block-iter vs 1024 MMA cycles -> tensor-bound.
// Pads: As stride 136, Ws stride 264 (both ==8 mod 32: fragment LDS
// pattern (8q+g) covers all 32 banks, conflict-free).
// =====================================================================
__global__ void __launch_bounds__(256, 1) gemm_tf32_nt(const float* __restrict__ A,
                                                       const float* __restrict__ W,
                                                       float* __restrict__ Cmat,
                                                       int M, int N, int K) {
    __shared__ unsigned As[2][16][136];
    __shared__ unsigned Ws[2][16][264];

    const int tid  = threadIdx.x;
    const int warp = tid >> 5;
    const int lane = tid & 31;
    const int g    = lane >> 2;       // 0..7
    const int q    = lane & 3;        // 0..3
    const int bm = blockIdx.y * 128;
    const int bn = blockIdx.x * 256;
    const int wm = (warp & 1) * 64;   // warp m offset
    const int wn = (warp >> 1) * 64;  // warp n offset

    // global-load assignment
    const int lmA = tid & 127;        // A: row, 2 float4 in k
    const int lkA = (tid >> 7) * 8;   // 0 or 8
    const int lnB = tid;              // W: one full row of 16 k per thread

    const float* Ap = A + (size_t)(bm + lmA) * K + lkA;
    const float* Wp = W + (size_t)(bn + lnB) * K;

    float acc[4][8][4];
#pragma unroll
    for (int mi = 0; mi < 4; mi++)
#pragma unroll
        for (int ni = 0; ni < 8; ni++)
#pragma unroll
            for (int c = 0; c < 4; c++) acc[mi][ni][c] = 0.f;

    // ---- preload stage 0 ----
    {
        float4 a1 = *(const float4*)(Ap);
        float4 a2 = *(const float4*)(Ap + 4);
        float4 w0 = *(const float4*)(Wp);
        float4 w1 = *(const float4*)(Wp + 4);
        float4 w2 = *(const float4*)(Wp + 8);
        float4 w3 = *(const float4*)(Wp + 12);
        As[0][lkA + 0][lmA] = f2tf32(a1.x); As[0][lkA + 1][lmA] = f2tf32(a1.y);
        As[0][lkA + 2][lmA] = f2tf32(a1.z); As[0][lkA + 3][lmA] = f2tf32(a1.w);
        As[0][lkA + 4][lmA] = f2tf32(a2.x); As[0][lkA + 5][lmA] = f2tf32(a2.y);
        As[0][lkA + 6][lmA] = f2tf32(a2.z); As[0][lkA + 7][lmA] = f2tf32(a2.w);
        Ws[0][ 0][lnB] = f2tf32(w0.x); Ws[0][ 1][lnB] = f2tf32(w0.y);
        Ws[0][ 2][lnB] = f2tf32(w0.z); Ws[0][ 3][lnB] = f2tf32(w0.w);
        Ws[0][ 4][lnB] = f2tf32(w1.x); Ws[0][ 5][lnB] = f2tf32(w1.y);
        Ws[0][ 6][lnB] = f2tf32(w1.z); Ws[0][ 7][lnB] = f2tf32(w1.w);
        Ws[0][ 8][lnB] = f2tf32(w2.x); Ws[0][ 9][lnB] = f2tf32(w2.y);
        Ws[0][10][lnB] = f2tf32(w2.z); Ws[0][11][lnB] = f2tf32(w2.w);
        Ws[0][12][lnB] = f2tf32(w3.x); Ws[0][13][lnB] = f2tf32(w3.y);
        Ws[0][14][lnB] = f2tf32(w3.z); Ws[0][15][lnB] = f2tf32(w3.w);
    }
    __syncthreads();

    int buf = 0;
    for (int k0 = 0; k0 < K; k0 += 16) {
        const bool more = (k0 + 16) < K;
        float4 a1, a2, w0, w1, w2, w3;
        if (more) {
            a1 = *(const float4*)(Ap + k0 + 16);
            a2 = *(const float4*)(Ap + k0 + 20);
            w0 = *(const float4*)(Wp + k0 + 16);
            w1 = *(const float4*)(Wp + k0 + 20);
            w2 = *(const float4*)(Wp + k0 + 24);
            w3 = *(const float4*)(Wp + k0 + 28);
        }

        // ---- compute on stage `buf` ----
#pragma unroll
        for (int ks = 0; ks < 2; ks++) {
            const int kk = ks * 8;
            unsigned af[4][4];
#pragma unroll
            for (int mi = 0; mi < 4; mi++) {
                const int m = wm + mi * 16;
                af[mi][0] = As[buf][kk + q][m + g];
                af[mi][1] = As[buf][kk + q][m + g + 8];
                af[mi][2] = As[buf][kk + q + 4][m + g];
                af[mi][3] = As[buf][kk + q + 4][m + g + 8];
            }
            unsigned bf[8][2];
#pragma unroll
            for (int ni = 0; ni < 8; ni++) {
                const int n = wn + ni * 8;
                bf[ni][0] = Ws[buf][kk + q][n + g];
                bf[ni][1] = Ws[buf][kk + q + 4][n + g];
            }
#pragma unroll
            for (int mi = 0; mi < 4; mi++)
#pragma unroll
                for (int ni = 0; ni < 8; ni++)
                    mma_tf32(acc[mi][ni][0], acc[mi][ni][1], acc[mi][ni][2], acc[mi][ni][3],
                             af[mi][0], af[mi][1], af[mi][2], af[mi][3],
                             bf[ni][0], bf[ni][1]);
        }

        if (more) {
            const int nb = buf ^ 1;
            As[nb][lkA + 0][lmA] = f2tf32(a1.x); As[nb][lkA + 1][lmA] = f2tf32(a1.y);
            As[nb][lkA + 2][lmA] = f2tf32(a1.z); As[nb][lkA + 3][lmA] = f2tf32(a1.w);
            As[nb][lkA + 4][lmA] = f2tf32(a2.x); As[nb][lkA + 5][lmA] = f2tf32(a2.y);
            As[nb][lkA + 6][lmA] = f2tf32(a2.z); As[nb][lkA + 7][lmA] = f2tf32(a2.w);
            Ws[nb][ 0][lnB] = f2tf32(w0.x); Ws[nb][ 1][lnB] = f2tf32(w0.y);
            Ws[nb][ 2][lnB] = f2tf32(w0.z); Ws[nb][ 3][lnB] = f2tf32(w0.w);
            Ws[nb][ 4][lnB] = f2tf32(w1.x); Ws[nb][ 5][lnB] = f2tf32(w1.y);
            Ws[nb][ 6][lnB] = f2tf32(w1.z); Ws[nb][ 7][lnB] = f2tf32(w1.w);
            Ws[nb][ 8][lnB] = f2tf32(w2.x); Ws[nb][ 9][lnB] = f2tf32(w2.y);
            Ws[nb][10][lnB] = f2tf32(w2.z); Ws[nb][11][lnB] = f2tf32(w2.w);
            Ws[nb][12][lnB] = f2tf32(w3.x); Ws[nb][13][lnB] = f2tf32(w3.y);
            Ws[nb][14][lnB] = f2tf32(w3.z); Ws[nb][15][lnB] = f2tf32(w3.w);
            __syncthreads();
            buf = nb;
        }
    }

    // epilogue
#pragma unroll
    for (int mi = 0; mi < 4; mi++) {
#pragma unroll
        for (int ni = 0; ni < 8; ni++) {
            const int m = bm + wm + mi * 16 + g;
            const int n = bn + wn + ni * 8 + 2 * q;
            *(float2*)&Cmat[(size_t)m * N + n] =
                make_float2(acc[mi][ni][0], acc[mi][ni][1]);
            *(float2*)&Cmat[(size_t)(m + 8) * N + n] =
                make_float2(acc[mi][ni][2], acc[mi][ni][3]);
        }
    }
}

// =====================================================================
// RoPE + split qkv[8192][1536] -> g_q/g_k/g_v in [bh][t][d] layout.
// =====================================================================
__global__ void __launch_bounds__(256) rope_split(const float* __restrict__ qkv,
                                                  const float* __restrict__ cosp,
                                                  const float* __restrict__ sinp,
                                                  float* __restrict__ q,
                                                  float* __restrict__ k,
                                                  float* __restrict__ v) {
    int idx = blockIdx.x * blockDim.x + threadIdx.x;   // 32*2048*32
    int d  = idx & 31;
    int t  = (idx >> 5) & (TT - 1);
    int bh = idx >> 16;
    int b = bh >> 3, h = bh & 7;

    size_t rowq = (size_t)(b * TT + t) * (3 * CC);
    int c = h * HD + d;
    float c1 = cosp[t * HD + d],      s1 = sinp[t * HD + d];
    float c2 = cosp[t * HD + d + 32], s2 = sinp[t * HD + d + 32];
    size_t dst = (size_t)(bh * TT + t) * HD + d;

    float x1 = qkv[rowq + c];
    float x2 = qkv[rowq + c + 32];
    q[dst]      = x1 * c1 - x2 * s1;
    q[dst + 32] = x2 * c2 + x1 * s2;

    x1 = qkv[rowq + CC + c];
    x2 = qkv[rowq + CC + c + 32];
    k[dst]      = x1 * c1 - x2 * s1;
    k[dst + 32] = x2 * c2 + x1 * s2;

    v[dst]      = qkv[rowq + 2 * CC + c];
    v[dst + 32] = qkv[rowq + 2 * CC + c + 32];
}

// =====================================================================
// Flash attention (causal) on tensor cores: mma.sync m16n8k8 tf32.
// =====================================================================
__global__ void __launch_bounds__(128) attn_tc(const float* __restrict__ Q,
                                               const float* __restrict__ K,
                                               const float* __restrict__ V,
                                               float* __restrict__ Oatt) {
    __shared__ unsigned Ks[64][76];   // stride 76: (12g+q)%32 all-distinct
    __shared__ unsigned Vs[64][72];   // stride 72: (8q+g)%32 all-distinct

    const int tid  = threadIdx.x;
    const int warp = tid >> 5;
    const int lane = tid & 31;
    const int g    = lane >> 2;
    const int q    = lane & 3;
    const int qt   = (int)gridDim.x - 1 - (int)blockIdx.x;  // big tiles first
    const int q0   = qt * 64;
    const int bh   = blockIdx.y;
    const int row0 = q0 + warp * 16 + g;
    const int row1 = row0 + 8;

    unsigned Qa[8][4];
    {
        const float* q0p = Q + ((size_t)bh * TT + row0) * HD;
        const float* q1p = Q + ((size_t)bh * TT + row1) * HD;
#pragma unroll
        for (int k = 0; k < 8; k++) {
            Qa[k][0] = f2tf32(0.125f * q0p[8 * k + q]);
            Qa[k][1] = f2tf32(0.125f * q1p[8 * k + q]);
            Qa[k][2] = f2tf32(0.125f * q0p[8 * k + q + 4]);
            Qa[k][3] = f2tf32(0.125f * q1p[8 * k + q + 4]);
        }
    }

    float Oac[8][4];
#pragma unroll
    for (int j = 0; j < 8; j++)
#pragma unroll
        for (int i = 0; i < 4; i++) Oac[j][i] = 0.f;
    float m0_ = -1e30f, m1_ = -1e30f, l0_ = 0.f, l1_ = 0.f;

    const int la = 4 * g + (q >> 1);
    const int lb = la + 2;
    const bool odd = (q & 1);

    const int nkt = qt + 1;
    for (int kt = 0; kt < nkt; kt++) {
        const int k0 = kt * 64;
        __syncthreads();
        {
            const float* kb = K + ((size_t)bh * TT + k0) * HD;
            const float* vb = V + ((size_t)bh * TT + k0) * HD;
#pragma unroll
            for (int i = 0; i < 8; i++) {
                int idx4 = tid + i * 128;
                int row = idx4 >> 4, col = (idx4 & 15) * 4;
                float4 a = *(const float4*)(kb + row * HD + col);
                float4 b = *(const float4*)(vb + row * HD + col);
                *(uint4*)&Ks[row][col] = make_uint4(f2tf32(a.x), f2tf32(a.y),
                                                    f2tf32(a.z), f2tf32(a.w));
                *(uint4*)&Vs[row][col] = make_uint4(f2tf32(b.x), f2tf32(b.y),
                                                    f2tf32(b.z), f2tf32(b.w));
            }
        }
        __syncthreads();

        float S[8][4];
#pragma unroll
        for (int j = 0; j < 8; j++)
#pragma unroll
            for (int i = 0; i < 4; i++) S[j][i] = 0.f;

#pragma unroll
        for (int k = 0; k < 8; k++) {
#pragma unroll
            for (int j = 0; j < 8; j++) {
                unsigned b0 = Ks[8 * j + g][8 * k + q];
                unsigned b1 = Ks[8 * j + g][8 * k + q + 4];
                mma_tf32(S[j][0], S[j][1], S[j][2], S[j][3],
                         Qa[k][0], Qa[k][1], Qa[k][2], Qa[k][3], b0, b1);
            }
        }

        if (kt == nkt - 1) {
#pragma unroll
            for (int j = 0; j < 8; j++) {
                int c = k0 + 8 * j + 2 * q;
                if (c     > row0) S[j][0] = -1e30f;
                if (c + 1 > row0) S[j][1] = -1e30f;
                if (c     > row1) S[j][2] = -1e30f;
                if (c + 1 > row1) S[j][3] = -1e30f;
            }
        }

        float tm0 = -1e30f, tm1 = -1e30f;
#pragma unroll
        for (int j = 0; j < 8; j++) {
            tm0 = fmaxf(tm0, fmaxf(S[j][0], S[j][1]));
            tm1 = fmaxf(tm1, fmaxf(S[j][2], S[j][3]));
        }
        tm0 = fmaxf(tm0, __shfl_xor_sync(0xffffffffu, tm0, 1));
        tm0 = fmaxf(tm0, __shfl_xor_sync(0xffffffffu, tm0, 2));
        tm1 = fmaxf(tm1, __shfl_xor_sync(0xffffffffu, tm1, 1));
        tm1 = fmaxf(tm1, __shfl_xor_sync(0xffffffffu, tm1, 2));

        float nm0 = fmaxf(m0_, tm0), nm1 = fmaxf(m1_, tm1);
        float r0 = __expf(m0_ - nm0), r1 = __expf(m1_ - nm1);
        m0_ = nm0; m1_ = nm1;

        float rs0 = 0.f, rs1 = 0.f;
#pragma unroll
        for (int j = 0; j < 8; j++) {
            S[j][0] = __expf(S[j][0] - nm0);
            S[j][1] = __expf(S[j][1] - nm0);
            S[j][2] = __expf(S[j][2] - nm1);
            S[j][3] = __expf(S[j][3] - nm1);
            rs0 += S[j][0] + S[j][1];
            rs1 += S[j][2] + S[j][3];
        }
        rs0 += __shfl_xor_sync(0xffffffffu, rs0, 1);
        rs0 += __shfl_xor_sync(0xffffffffu, rs0, 2);
        rs1 += __shfl_xor_sync(0xffffffffu, rs1, 1);
        rs1 += __shfl_xor_sync(0xffffffffu, rs1, 2);
        l0_ = l0_ * r0 + rs0;
        l1_ = l1_ * r1 + rs1;

#pragma unroll
        for (int j = 0; j < 8; j++) {
            Oac[j][0] *= r0; Oac[j][1] *= r0;
            Oac[j][2] *= r1; Oac[j][3] *= r1;
        }

#pragma unroll
        for (int k = 0; k < 8; k++) {
            float w00 = __shfl_sync(0xffffffffu, S[k][0], la);
            float w01 = __shfl_sync(0xffffffffu, S[k][1], la);
            float w10 = __shfl_sync(0xffffffffu, S[k][0], lb);
            float w11 = __shfl_sync(0xffffffffu, S[k][1], lb);
            unsigned a0 = f2tf32(odd ? w01 : w00);
            unsigned a2 = f2tf32(odd ? w11 : w10);
            float x00 = __shfl_sync(0xffffffffu, S[k][2], la);
            float x01 = __shfl_sync(0xffffffffu, S[k][3], la);
            float x10 = __shfl_sync(0xffffffffu, S[k][2], lb);
            float x11 = __shfl_sync(0xffffffffu, S[k][3], lb);
            unsigned a1 = f2tf32(odd ? x01 : x00);
            unsigned a3 = f2tf32(odd ? x11 : x10);
#pragma unroll
            for (int j = 0; j < 8; j++) {
                unsigned b0 = Vs[8 * k + q][8 * j + g];
                unsigned b1 = Vs[8 * k + q + 4][8 * j + g];
                mma_tf32(Oac[j][0], Oac[j][1], Oac[j][2], Oac[j][3],
                         a0, a1, a2, a3, b0, b1);
            }
        }
    }

    const int b = bh >> 3, h = bh & 7;
    float inv0 = 1.f / l0_, inv1 = 1.f / l1_;
    float* o0 = Oatt + ((size_t)(b * TT) + row0) * CC + h * HD;
    float* o1 = Oatt + ((size_t)(b * TT) + row1) * CC + h * HD;
#pragma unroll
    for (int j = 0; j < 8; j++) {
        float2 v0 = make_float2(Oac[j][0] * inv0, Oac[j][1] * inv0);
        float2 v1 = make_float2(Oac[j][2] * inv1, Oac[j][3] * inv1);
        *(float2*)&o0[8 * j + 2 * q] = v0;
        *(float2*)&o1[8 * j + 2 * q] = v1;
    }
}

// =====================================================================
extern "C" void kernel_launch(void* const* d_in, const int* in_sizes, int n_in,
                              void* d_out, int out_size) {
    const float* x    = (const float*)d_in[0];
    const float* cosp = (const float*)d_in[1];
    const float* sinp = (const float*)d_in[2];
    const float* Wqkv = (const float*)d_in[3];
    const float* Wout = (const float*)d_in[4];
    float* out = (float*)d_out;

    float *qkv, *q, *k, *v, *att;
    cudaGetSymbolAddress((void**)&qkv, g_qkv);
    cudaGetSymbolAddress((void**)&q,   g_q);
    cudaGetSymbolAddress((void**)&k,   g_k);
    cudaGetSymbolAddress((void**)&v,   g_v);
    cudaGetSymbolAddress((void**)&att, g_att);

    // 1) qkv = x @ Wqkv^T            (tf32 TC, 128x256 tiles)
    gemm_tf32_nt<<<dim3((3 * CC) / 256, MM / 128), 256>>>(x, Wqkv, qkv, MM, 3 * CC, CC);
    // 2) RoPE + split into head-major q/k/v
    rope_split<<<(BH * TT * 32) / 256, 256>>>(qkv, cosp, sinp, q, k, v);
    // 3) causal flash attention on tensor cores
    attn_tc<<<dim3(TT / 64, BH), 128>>>(q, k, v, att);
    // 4) out = att @ Wout^T          (tf32 TC, 128x256 tiles)
    gemm_tf32_nt<<<dim3(CC / 256, MM / 128), 256>>>(att, Wout, out, MM, CC, CC);
}

// round 8
// speedup vs baseline: 1.5263x; 1.4194x over previous
#include <cuda_runtime.h>
#include <cuda_fp16.h>
#include <cstdint>
#include <math.h>

// Problem constants
#define BB 4
#define TT 2048
#define CC 512
#define HH 8
#define HD 64
#define MM (BB*TT)          // 8192
#define BH (BB*HH)          // 32

// ---------------- device scratch ----------------
__device__ float g_qkv[MM * 3 * CC];
__device__ float g_q[BH * TT * HD];
__device__ float g_k[BH * TT * HD];
__device__ float g_v[BH * TT * HD];
__device__ float g_att[MM * CC];

// ---------------- fp16 helpers ----------------
__device__ __forceinline__ unsigned pack_h2(float x, float y) {
    __half2 h = __floats2half2_rn(x, y);
    return *(unsigned*)&h;
}

// mma.sync m16n8k16 fp16 -> f32
__device__ __forceinline__ void mma_f16(float& c0, float& c1, float& c2, float& c3,
                                        unsigned a0, unsigned a1, unsigned a2, unsigned a3,
                                        unsigned b0, unsigned b1) {
    asm volatile(
        "mma.sync.aligned.m16n8k16.row.col.f32.f16.f16.f32 "
        "{%0,%1,%2,%3}, {%4,%5,%6,%7}, {%8,%9}, {%0,%1,%2,%3};"
        : "+f"(c0), "+f"(c1), "+f"(c2), "+f"(c3)
        : "r"(a0), "r"(a1), "r"(a2), "r"(a3), "r"(b0), "r"(b1));
}

// =====================================================================
// FP16 tensor-core GEMM: C[M,N] = A[M,K] @ W[N,K]^T
// Block tile 128x256, 8 warps 2(m)x4(n), warp tile 64x64, BK=32,
// double-buffered. Smem half2: As2[k2][m] stride 136, Ws2[k2][n]
// stride 264 (both ==8 mod 32: fragment LDS (8q+g) covers all banks).
// =====================================================================
__global__ void __launch_bounds__(256, 1) gemm_h_nt(const float* __restrict__ A,
                                                    const float* __restrict__ W,
                                                    float* __restrict__ Cmat,
                                                    int M, int N, int K) {
    __shared__ unsigned As2[2][16][136];   // half2 as unsigned
    __shared__ unsigned Ws2[2][16][264];

    const int tid  = threadIdx.x;
    const int warp = tid >> 5;
    const int lane = tid & 31;
    const int g    = lane >> 2;       // 0..7
    const int q    = lane & 3;        // 0..3
    const int bm = blockIdx.y * 128;
    const int bn = blockIdx.x * 256;
    const int wm = (warp & 1) * 64;
    const int wn = (warp >> 1) * 64;

    const int lmA  = tid & 127;       // A row
    const int lkA  = (tid >> 7) * 16; // A k offset (0 or 16)
    const int lkA2 = lkA >> 1;        // k2 offset (0 or 8)

    const float* Ap = A + (size_t)(bm + lmA) * K + lkA;
    const float* Wp = W + (size_t)(bn + tid) * K;

    float acc[4][8][4];
#pragma unroll
    for (int mi = 0; mi < 4; mi++)
#pragma unroll
        for (int ni = 0; ni < 8; ni++)
#pragma unroll
            for (int c = 0; c < 4; c++) acc[mi][ni][c] = 0.f;

    float4 av[4], wv[8];
#pragma unroll
    for (int i = 0; i < 4; i++) av[i] = *(const float4*)(Ap + 4 * i);
#pragma unroll
    for (int i = 0; i < 8; i++) wv[i] = *(const float4*)(Wp + 4 * i);

#pragma unroll
    for (int i = 0; i < 4; i++) {
        As2[0][lkA2 + 2 * i    ][lmA] = pack_h2(av[i].x, av[i].y);
        As2[0][lkA2 + 2 * i + 1][lmA] = pack_h2(av[i].z, av[i].w);
    }
#pragma unroll
    for (int i = 0; i < 8; i++) {
        Ws2[0][2 * i    ][tid] = pack_h2(wv[i].x, wv[i].y);
        Ws2[0][2 * i + 1][tid] = pack_h2(wv[i].z, wv[i].w);
    }
    __syncthreads();

    int buf = 0;
    for (int k0 = 0; k0 < K; k0 += 32) {
        const bool more = (k0 + 32) < K;
        if (more) {
#pragma unroll
            for (int i = 0; i < 4; i++) av[i] = *(const float4*)(Ap + k0 + 32 + 4 * i);
#pragma unroll
            for (int i = 0; i < 8; i++) wv[i] = *(const float4*)(Wp + k0 + 32 + 4 * i);
        }

        // ---- compute: 2 k-chunks of 16 ----
#pragma unroll
        for (int c = 0; c < 2; c++) {
            const int k2 = 8 * c;
            unsigned af[4][4];
#pragma unroll
            for (int mi = 0; mi < 4; mi++) {
                const int m = wm + mi * 16;
                af[mi][0] = As2[buf][k2 + q    ][m + g];
                af[mi][1] = As2[buf][k2 + q    ][m + g + 8];
                af[mi][2] = As2[buf][k2 + q + 4][m + g];
                af[mi][3] = As2[buf][k2 + q + 4][m + g + 8];
            }
            unsigned bf[8][2];
#pragma unroll
            for (int ni = 0; ni < 8; ni++) {
                const int n = wn + ni * 8;
                bf[ni][0] = Ws2[buf][k2 + q    ][n + g];
                bf[ni][1] = Ws2[buf][k2 + q + 4][n + g];
            }
#pragma unroll
            for (int mi = 0; mi < 4; mi++)
#pragma unroll
                for (int ni = 0; ni < 8; ni++)
                    mma_f16(acc[mi][ni][0], acc[mi][ni][1], acc[mi][ni][2], acc[mi][ni][3],
                            af[mi][0], af[mi][1], af[mi][2], af[mi][3],
                            bf[ni][0], bf[ni][1]);
        }

        if (more) {
            const int nb = buf ^ 1;
#pragma unroll
            for (int i = 0; i < 4; i++) {
                As2[nb][lkA2 + 2 * i    ][lmA] = pack_h2(av[i].x, av[i].y);
                As2[nb][lkA2 + 2 * i + 1][lmA] = pack_h2(av[i].z, av[i].w);
            }
#pragma unroll
            for (int i = 0; i < 8; i++) {
                Ws2[nb][2 * i    ][tid] = pack_h2(wv[i].x, wv[i].y);
                Ws2[nb][2 * i + 1][tid] = pack_h2(wv[i].z, wv[i].w);
            }
            __syncthreads();
            buf = nb;
        }
    }

    // epilogue
#pragma unroll
    for (int mi = 0; mi < 4; mi++) {
#pragma unroll
        for (int ni = 0; ni < 8; ni++) {
            const int m = bm + wm + mi * 16 + g;
            const int n = bn + wn + ni * 8 + 2 * q;
            *(float2*)&Cmat[(size_t)m * N + n] =
                make_float2(acc[mi][ni][0], acc[mi][ni][1]);
            *(float2*)&Cmat[(size_t)(m + 8) * N + n] =
                make_float2(acc[mi][ni][2], acc[mi][ni][3]);
        }
    }
}

// =====================================================================
// RoPE + split qkv[8192][1536] -> g_q/g_k/g_v in [bh][t][d] layout.
// =====================================================================
__global__ void __launch_bounds__(256) rope_split(const float* __restrict__ qkv,
                                                  const float* __restrict__ cosp,
                                                  const float* __restrict__ sinp,
                                                  float* __restrict__ q,
                                                  float* __restrict__ k,
                                                  float* __restrict__ v) {
    int idx = blockIdx.x * blockDim.x + threadIdx.x;   // 32*2048*32
    int d  = idx & 31;
    int t  = (idx >> 5) & (TT - 1);
    int bh = idx >> 16;
    int b = bh >> 3, h = bh & 7;

    size_t rowq = (size_t)(b * TT + t) * (3 * CC);
    int c = h * HD + d;
    float c1 = cosp[t * HD + d],      s1 = sinp[t * HD + d];
    float c2 = cosp[t * HD + d + 32], s2 = sinp[t * HD + d + 32];
    size_t dst = (size_t)(bh * TT + t) * HD + d;

    float x1 = qkv[rowq + c];
    float x2 = qkv[rowq + c + 32];
    q[dst]      = x1 * c1 - x2 * s1;
    q[dst + 32] = x2 * c2 + x1 * s2;

    x1 = qkv[rowq + CC + c];
    x2 = qkv[rowq + CC + c + 32];
    k[dst]      = x1 * c1 - x2 * s1;
    k[dst + 32] = x2 * c2 + x1 * s2;

    v[dst]      = qkv[rowq + 2 * CC + c];
    v[dst + 32] = qkv[rowq + 2 * CC + c + 32];
}

// =====================================================================
// Flash attention (causal), fp16 mma m16n8k16.
// Block 128 thr / 4 warps, q-tile 64 (16/warp), k-tile 64.
// Ks2[key][d2] stride 36 (==4 mod 32: S-frag banks 4g+q distinct).
// Vs2[keypair][d] stride 72 (==8 mod 32: PV-frag banks 8q+g distinct),
//   half2 packs (even key, odd key) for the same d; 64 d-columns.
// P A-fragment == S C-fragment -> zero shuffles.
// =====================================================================
__global__ void __launch_bounds__(128) attn_h(const float* __restrict__ Q,
                                              const float* __restrict__ K,
                                              const float* __restrict__ V,
                                              float* __restrict__ Oatt) {
    __shared__ unsigned Ks2[64][36];   // half2 {d, d+1} per key
    __shared__ unsigned Vs2[32][72];   // half2 {key even, key odd} per d, d<64

    const int tid  = threadIdx.x;
    const int warp = tid >> 5;
    const int lane = tid & 31;
    const int g    = lane >> 2;
    const int q    = lane & 3;
    const int qt   = (int)gridDim.x - 1 - (int)blockIdx.x;  // big tiles first
    const int q0   = qt * 64;
    const int bh   = blockIdx.y;
    const int row0 = q0 + warp * 16 + g;
    const int row1 = row0 + 8;

    // ---- Q fragments (scaled by 1/8), fp16-packed ----
    unsigned Qa[4][4];
    {
        const float* q0p = Q + ((size_t)bh * TT + row0) * HD;
        const float* q1p = Q + ((size_t)bh * TT + row1) * HD;
#pragma unroll
        for (int kc = 0; kc < 4; kc++) {
            int d0 = 16 * kc + 2 * q;
            Qa[kc][0] = pack_h2(0.125f * q0p[d0],     0.125f * q0p[d0 + 1]);
            Qa[kc][1] = pack_h2(0.125f * q1p[d0],     0.125f * q1p[d0 + 1]);
            Qa[kc][2] = pack_h2(0.125f * q0p[d0 + 8], 0.125f * q0p[d0 + 9]);
            Qa[kc][3] = pack_h2(0.125f * q1p[d0 + 8], 0.125f * q1p[d0 + 9]);
        }
    }

    float Oac[8][4];
#pragma unroll
    for (int j = 0; j < 8; j++)
#pragma unroll
        for (int i = 0; i < 4; i++) Oac[j][i] = 0.f;
    float m0_ = -1e30f, m1_ = -1e30f, l0_ = 0.f, l1_ = 0.f;

    const int nkt = qt + 1;
    for (int kt = 0; kt < nkt; kt++) {
        const int k0 = kt * 64;
        __syncthreads();
        {
            const float* kb = K + ((size_t)bh * TT + k0) * HD;
            const float* vb = V + ((size_t)bh * TT + k0) * HD;
            __half* Vsh = (__half*)Vs2;     // [32][144] halves
#pragma unroll
            for (int i = 0; i < 8; i++) {
                int idx4 = tid + i * 128;          // 0..1023
                int key = idx4 >> 4, c4 = idx4 & 15;
                int d = 4 * c4;
                float4 a = *(const float4*)(kb + (size_t)key * HD + d);
                float4 b = *(const float4*)(vb + (size_t)key * HD + d);
                // K: two half2 (contiguous d) -> one 8B store
                uint2 kk2 = make_uint2(pack_h2(a.x, a.y), pack_h2(a.z, a.w));
                *(uint2*)&Ks2[key][2 * c4] = kk2;
                // V: 4 halves scattered into key-pair-packed layout
                __half* vp = Vsh + (key >> 1) * 144 + 2 * d + (key & 1);
                vp[0] = __float2half_rn(b.x);
                vp[2] = __float2half_rn(b.y);
                vp[4] = __float2half_rn(b.z);
                vp[6] = __float2half_rn(b.w);
            }
        }
        __syncthreads();

        // ---- S = (Q/8) @ K^T : 8 n-blocks x 4 k-chunks ----
        float S[8][4];
#pragma unroll
        for (int j = 0; j < 8; j++)
#pragma unroll
            for (int i = 0; i < 4; i++) S[j][i] = 0.f;

#pragma unroll
        for (int kc = 0; kc < 4; kc++) {
#pragma unroll
            for (int j = 0; j < 8; j++) {
                unsigned b0 = Ks2[8 * j + g][8 * kc + q];
                unsigned b1 = Ks2[8 * j + g][8 * kc + q + 4];
                mma_f16(S[j][0], S[j][1], S[j][2], S[j][3],
                        Qa[kc][0], Qa[kc][1], Qa[kc][2], Qa[kc][3], b0, b1);
            }
        }

        // ---- causal mask (diagonal tile only) ----
        if (kt == nkt - 1) {
#pragma unroll
            for (int j = 0; j < 8; j++) {
                int c = k0 + 8 * j + 2 * q;
                if (c     > row0) S[j][0] = -1e30f;
                if (c + 1 > row0) S[j][1] = -1e30f;
                if (c     > row1) S[j][2] = -1e30f;
                if (c + 1 > row1) S[j][3] = -1e30f;
            }
        }

        // ---- online softmax ----
        float tm0 = -1e30f, tm1 = -1e30f;
#pragma unroll
        for (int j = 0; j < 8; j++) {
            tm0 = fmaxf(tm0, fmaxf(S[j][0], S[j][1]));
            tm1 = fmaxf(tm1, fmaxf(S[j][2], S[j][3]));
        }
        tm0 = fmaxf(tm0, __shfl_xor_sync(0xffffffffu, tm0, 1));
        tm0 = fmaxf(tm0, __shfl_xor_sync(0xffffffffu, tm0, 2));
        tm1 = fmaxf(tm1, __shfl_xor_sync(0xffffffffu, tm1, 1));
        tm1 = fmaxf(tm1, __shfl_xor_sync(0xffffffffu, tm1, 2));

        float nm0 = fmaxf(m0_, tm0), nm1 = fmaxf(m1_, tm1);
        float r0 = __expf(m0_ - nm0), r1 = __expf(m1_ - nm1);
        m0_ = nm0; m1_ = nm1;

        float rs0 = 0.f, rs1 = 0.f;
#pragma unroll
        for (int j = 0; j < 8; j++) {
            S[j][0] = __expf(S[j][0] - nm0);
            S[j][1] = __expf(S[j][1] - nm0);
            S[j][2] = __expf(S[j][2] - nm1);
            S[j][3] = __expf(S[j][3] - nm1);
            rs0 += S[j][0] + S[j][1];
            rs1 += S[j][2] + S[j][3];
        }
        rs0 += __shfl_xor_sync(0xffffffffu, rs0, 1);
        rs0 += __shfl_xor_sync(0xffffffffu, rs0, 2);
        rs1 += __shfl_xor_sync(0xffffffffu, rs1, 1);
        rs1 += __shfl_xor_sync(0xffffffffu, rs1, 2);
        l0_ = l0_ * r0 + rs0;
        l1_ = l1_ * r1 + rs1;

#pragma unroll
        for (int j = 0; j < 8; j++) {
            Oac[j][0] *= r0; Oac[j][1] *= r0;
            Oac[j][2] *= r1; Oac[j][3] *= r1;
        }

        // ---- O += P @ V : P A-frag == S C-frag (no shuffles) ----
#pragma unroll
        for (int kc = 0; kc < 4; kc++) {
            unsigned a0 = pack_h2(S[2 * kc][0],     S[2 * kc][1]);
            unsigned a1 = pack_h2(S[2 * kc][2],     S[2 * kc][3]);
            unsigned a2 = pack_h2(S[2 * kc + 1][0], S[2 * kc + 1][1]);
            unsigned a3 = pack_h2(S[2 * kc + 1][2], S[2 * kc + 1][3]);
#pragma unroll
            for (int j = 0; j < 8; j++) {
                unsigned b0 = Vs2[8 * kc + q][8 * j + g];
                unsigned b1 = Vs2[8 * kc + q + 4][8 * j + g];
                mma_f16(Oac[j][0], Oac[j][1], Oac[j][2], Oac[j][3],
                        a0, a1, a2, a3, b0, b1);
            }
        }
    }

    // ---- epilogue ----
    const int b = bh >> 3, h = bh & 7;
    float inv0 = 1.f / l0_, inv1 = 1.f / l1_;
    float* o0 = Oatt + ((size_t)(b * TT) + row0) * CC + h * HD;
    float* o1 = Oatt + ((size_t)(b * TT) + row1) * CC + h * HD;
#pragma unroll
    for (int j = 0; j < 8; j++) {
        float2 v0 = make_float2(Oac[j][0] * inv0, Oac[j][1] * inv0);
        float2 v1 = make_float2(Oac[j][2] * inv1, Oac[j][3] * inv1);
        *(float2*)&o0[8 * j + 2 * q] = v0;
        *(float2*)&o1[8 * j + 2 * q] = v1;
    }
}

// =====================================================================
extern "C" void kernel_launch(void* const* d_in, const int* in_sizes, int n_in,
                              void* d_out, int out_size) {
    const float* x    = (const float*)d_in[0];
    const float* cosp = (const float*)d_in[1];
    const float* sinp = (const float*)d_in[2];
    const float* Wqkv = (const float*)d_in[3];
    const float* Wout = (const float*)d_in[4];
    float* out = (float*)d_out;

    float *qkv, *q, *k, *v, *att;
    cudaGetSymbolAddress((void**)&qkv, g_qkv);
    cudaGetSymbolAddress((void**)&q,   g_q);
    cudaGetSymbolAddress((void**)&k,   g_k);
    cudaGetSymbolAddress((void**)&v,   g_v);
    cudaGetSymbolAddress((void**)&att, g_att);

    // 1) qkv = x @ Wqkv^T            (fp16 TC, 128x256 tiles)
    gemm_h_nt<<<dim3((3 * CC) / 256, MM / 128), 256>>>(x, Wqkv, qkv, MM, 3 * CC, CC);
    // 2) RoPE + split into head-major q/k/v
    rope_split<<<(BH * TT * 32) / 256, 256>>>(qkv, cosp, sinp, q, k, v);
    // 3) causal flash attention (fp16 TC)
    attn_h<<<dim3(TT / 64, BH), 128>>>(q, k, v, att);
    // 4) out = att @ Wout^T          (fp16 TC, 128x256 tiles)
    gemm_h_nt<<<dim3(CC / 256, MM / 128), 256>>>(att, Wout, out, MM, CC, CC);
}

// round 9
// speedup vs baseline: 1.5470x; 1.0136x over previous
#include <cuda_runtime.h>
#include <cuda_fp16.h>
#include <cstdint>
#include <math.h>

// Problem constants
#define BB 4
#define TT 2048
#define CC 512
#define HH 8
#define HD 64
#define MM (BB*TT)          // 8192
#define BH (BB*HH)          // 32

// ---------------- device scratch ----------------
__device__ float g_q[BH * TT * HD];
__device__ float g_k[BH * TT * HD];
__device__ float g_v[BH * TT * HD];
__device__ float g_att[MM * CC];

// ---------------- fp16 helpers ----------------
__device__ __forceinline__ unsigned pack_h2(float x, float y) {
    __half2 h = __floats2half2_rn(x, y);
    return *(unsigned*)&h;
}

// mma.sync m16n8k16 fp16 -> f32
__device__ __forceinline__ void mma_f16(float& c0, float& c1, float& c2, float& c3,
                                        unsigned a0, unsigned a1, unsigned a2, unsigned a3,
                                        unsigned b0, unsigned b1) {
    asm volatile(
        "mma.sync.aligned.m16n8k16.row.col.f32.f16.f16.f32 "
        "{%0,%1,%2,%3}, {%4,%5,%6,%7}, {%8,%9}, {%0,%1,%2,%3};"
        : "+f"(c0), "+f"(c1), "+f"(c2), "+f"(c3)
        : "r"(a0), "r"(a1), "r"(a2), "r"(a3), "r"(b0), "r"(b1));
}

// =====================================================================
// QKV GEMM + fused RoPE + head-split.
// C = x[8192,512] @ Wqkv[1536,512]^T; epilogue applies RoPE to q,k and
// scatters into g_q/g_k/g_v [bh][t][d]. Block 128x256, 8 warps 2x4,
// warp tile 64x64 (one head-aligned 64-col span per warp), BK=32,
// double-buffered fp16 smem.
// =====================================================================
__global__ void __launch_bounds__(256, 1) gemm_qkv_rope(const float* __restrict__ A,
                                                        const float* __restrict__ W,
                                                        const float* __restrict__ cosp,
                                                        const float* __restrict__ sinp,
                                                        float* __restrict__ qo,
                                                        float* __restrict__ ko,
                                                        float* __restrict__ vo) {
    const int Kd = CC;                 // 512
    __shared__ unsigned As2[2][16][136];
    __shared__ unsigned Ws2[2][16][264];

    const int tid  = threadIdx.x;
    const int warp = tid >> 5;
    const int lane = tid & 31;
    const int g    = lane >> 2;
    const int q    = lane & 3;
    const int bm = blockIdx.y * 128;
    const int bn = blockIdx.x * 256;
    const int wm = (warp & 1) * 64;
    const int wn = (warp >> 1) * 64;

    const int lmA  = tid & 127;
    const int lkA  = (tid >> 7) * 16;
    const int lkA2 = lkA >> 1;

    const float* Ap = A + (size_t)(bm + lmA) * Kd + lkA;
    const float* Wp = W + (size_t)(bn + tid) * Kd;

    float acc[4][8][4];
#pragma unroll
    for (int mi = 0; mi < 4; mi++)
#pragma unroll
        for (int ni = 0; ni < 8; ni++)
#pragma unroll
            for (int c = 0; c < 4; c++) acc[mi][ni][c] = 0.f;

    float4 av[4], wv[8];
#pragma unroll
    for (int i = 0; i < 4; i++) av[i] = *(const float4*)(Ap + 4 * i);
#pragma unroll
    for (int i = 0; i < 8; i++) wv[i] = *(const float4*)(Wp + 4 * i);

#pragma unroll
    for (int i = 0; i < 4; i++) {
        As2[0][lkA2 + 2 * i    ][lmA] = pack_h2(av[i].x, av[i].y);
        As2[0][lkA2 + 2 * i + 1][lmA] = pack_h2(av[i].z, av[i].w);
    }
#pragma unroll
    for (int i = 0; i < 8; i++) {
        Ws2[0][2 * i    ][tid] = pack_h2(wv[i].x, wv[i].y);
        Ws2[0][2 * i + 1][tid] = pack_h2(wv[i].z, wv[i].w);
    }
    __syncthreads();

    int buf = 0;
    for (int k0 = 0; k0 < Kd; k0 += 32) {
        const bool more = (k0 + 32) < Kd;
        if (more) {
#pragma unroll
            for (int i = 0; i < 4; i++) av[i] = *(const float4*)(Ap + k0 + 32 + 4 * i);
#pragma unroll
            for (int i = 0; i < 8; i++) wv[i] = *(const float4*)(Wp + k0 + 32 + 4 * i);
        }

#pragma unroll
        for (int c = 0; c < 2; c++) {
            const int k2 = 8 * c;
            unsigned af[4][4];
#pragma unroll
            for (int mi = 0; mi < 4; mi++) {
                const int m = wm + mi * 16;
                af[mi][0] = As2[buf][k2 + q    ][m + g];
                af[mi][1] = As2[buf][k2 + q    ][m + g + 8];
                af[mi][2] = As2[buf][k2 + q + 4][m + g];
                af[mi][3] = As2[buf][k2 + q + 4][m + g + 8];
            }
            unsigned bf[8][2];
#pragma unroll
            for (int ni = 0; ni < 8; ni++) {
                const int n = wn + ni * 8;
                bf[ni][0] = Ws2[buf][k2 + q    ][n + g];
                bf[ni][1] = Ws2[buf][k2 + q + 4][n + g];
            }
#pragma unroll
            for (int mi = 0; mi < 4; mi++)
#pragma unroll
                for (int ni = 0; ni < 8; ni++)
                    mma_f16(acc[mi][ni][0], acc[mi][ni][1], acc[mi][ni][2], acc[mi][ni][3],
                            af[mi][0], af[mi][1], af[mi][2], af[mi][3],
                            bf[ni][0], bf[ni][1]);
        }

        if (more) {
            const int nb = buf ^ 1;
#pragma unroll
            for (int i = 0; i < 4; i++) {
                As2[nb][lkA2 + 2 * i    ][lmA] = pack_h2(av[i].x, av[i].y);
                As2[nb][lkA2 + 2 * i + 1][lmA] = pack_h2(av[i].z, av[i].w);
            }
#pragma unroll
            for (int i = 0; i < 8; i++) {
                Ws2[nb][2 * i    ][tid] = pack_h2(wv[i].x, wv[i].y);
                Ws2[nb][2 * i + 1][tid] = pack_h2(wv[i].z, wv[i].w);
            }
            __syncthreads();
            buf = nb;
        }
    }

    // ---- fused epilogue: RoPE (q,k) + scatter to [bh][t][d] ----
    const int n0   = bn + wn;          // warp's first column: head-aligned
    const int type = n0 >> 9;          // 0=q, 1=k, 2=v
    const int h    = (n0 >> 6) & 7;
    float* outp = (type == 0) ? qo : (type == 1) ? ko : vo;

#pragma unroll
    for (int mi = 0; mi < 4; mi++) {
        const int m  = bm + wm + mi * 16 + g;      // row of c0,c1 (row+8 for c2,c3)
        const int b  = m >> 11;
        const int t0 = m & (TT - 1);
        const size_t base0 = ((size_t)(b * HH + h) * TT + t0) * HD;
        const size_t base1 = base0 + 8 * HD;       // t0+8 (same b, same head)

        if (type == 2) {
#pragma unroll
            for (int ni = 0; ni < 8; ni++) {
                const int d = ni * 8 + 2 * q;
                *(float2*)&outp[base0 + d] = make_float2(acc[mi][ni][0], acc[mi][ni][1]);
                *(float2*)&outp[base1 + d] = make_float2(acc[mi][ni][2], acc[mi][ni][3]);
            }
        } else {
#pragma unroll
            for (int ni = 0; ni < 4; ni++) {
                const int d  = ni * 8 + 2 * q;     // lower-half column pair
                const int du = d + 32;
                float2 cl0 = *(const float2*)&cosp[t0 * HD + d];
                float2 sl0 = *(const float2*)&sinp[t0 * HD + d];
                float2 cu0 = *(const float2*)&cosp[t0 * HD + du];
                float2 su0 = *(const float2*)&sinp[t0 * HD + du];
                float2 cl1 = *(const float2*)&cosp[(t0 + 8) * HD + d];
                float2 sl1 = *(const float2*)&sinp[(t0 + 8) * HD + d];
                float2 cu1 = *(const float2*)&cosp[(t0 + 8) * HD + du];
                float2 su1 = *(const float2*)&sinp[(t0 + 8) * HD + du];

                // row t0: x1 = c0/c1 of ni, x2 = c0/c1 of ni+4
                float x1a = acc[mi][ni][0],     x1b = acc[mi][ni][1];
                float x2a = acc[mi][ni + 4][0], x2b = acc[mi][ni + 4][1];
                *(float2*)&outp[base0 + d]  = make_float2(x1a * cl0.x - x2a * sl0.x,
                                                          x1b * cl0.y - x2b * sl0.y);
                *(float2*)&outp[base0 + du] = make_float2(x2a * cu0.x + x1a * su0.x,
                                                          x2b * cu0.y + x1b * su0.y);
                // row t0+8: x1 = c2/c3 of ni, x2 = c2/c3 of ni+4
                float y1a = acc[mi][ni][2],     y1b = acc[mi][ni][3];
                float y2a = acc[mi][ni + 4][2], y2b = acc[mi][ni + 4][3];
                *(float2*)&outp[base1 + d]  = make_float2(y1a * cl1.x - y2a * sl1.x,
                                                          y1b * cl1.y - y2b * sl1.y);
                *(float2*)&outp[base1 + du] = make_float2(y2a * cu1.x + y1a * su1.x,
                                                          y2b * cu1.y + y1b * su1.y);
            }
        }
    }
}

// =====================================================================
// FP16 tensor-core GEMM (plain epilogue) for the output projection.
// =====================================================================
__global__ void __launch_bounds__(256, 1) gemm_h_nt(const float* __restrict__ A,
                                                    const float* __restrict__ W,
                                                    float* __restrict__ Cmat,
                                                    int M, int N, int K) {
    __shared__ unsigned As2[2][16][136];
    __shared__ unsigned Ws2[2][16][264];

    const int tid  = threadIdx.x;
    const int warp = tid >> 5;
    const int lane = tid & 31;
    const int g    = lane >> 2;
    const int q    = lane & 3;
    const int bm = blockIdx.y * 128;
    const int bn = blockIdx.x * 256;
    const int wm = (warp & 1) * 64;
    const int wn = (warp >> 1) * 64;

    const int lmA  = tid & 127;
    const int lkA  = (tid >> 7) * 16;
    const int lkA2 = lkA >> 1;

    const float* Ap = A + (size_t)(bm + lmA) * K + lkA;
    const float* Wp = W + (size_t)(bn + tid) * K;

    float acc[4][8][4];
#pragma unroll
    for (int mi = 0; mi < 4; mi++)
#pragma unroll
        for (int ni = 0; ni < 8; ni++)
#pragma unroll
            for (int c = 0; c < 4; c++) acc[mi][ni][c] = 0.f;

    float4 av[4], wv[8];
#pragma unroll
    for (int i = 0; i < 4; i++) av[i] = *(const float4*)(Ap + 4 * i);
#pragma unroll
    for (int i = 0; i < 8; i++) wv[i] = *(const float4*)(Wp + 4 * i);

#pragma unroll
    for (int i = 0; i < 4; i++) {
        As2[0][lkA2 + 2 * i    ][lmA] = pack_h2(av[i].x, av[i].y);
        As2[0][lkA2 + 2 * i + 1][lmA] = pack_h2(av[i].z, av[i].w);
    }
#pragma unroll
    for (int i = 0; i < 8; i++) {
        Ws2[0][2 * i    ][tid] = pack_h2(wv[i].x, wv[i].y);
        Ws2[0][2 * i + 1][tid] = pack_h2(wv[i].z, wv[i].w);
    }
    __syncthreads();

    int buf = 0;
    for (int k0 = 0; k0 < K; k0 += 32) {
        const bool more = (k0 + 32) < K;
        if (more) {
#pragma unroll
            for (int i = 0; i < 4; i++) av[i] = *(const float4*)(Ap + k0 + 32 + 4 * i);
#pragma unroll
            for (int i = 0; i < 8; i++) wv[i] = *(const float4*)(Wp + k0 + 32 + 4 * i);
        }

#pragma unroll
        for (int c = 0; c < 2; c++) {
            const int k2 = 8 * c;
            unsigned af[4][4];
#pragma unroll
            for (int mi = 0; mi < 4; mi++) {
                const int m = wm + mi * 16;
                af[mi][0] = As2[buf][k2 + q    ][m + g];
                af[mi][1] = As2[buf][k2 + q    ][m + g + 8];
                af[mi][2] = As2[buf][k2 + q + 4][m + g];
                af[mi][3] = As2[buf][k2 + q + 4][m + g + 8];
            }
            unsigned bf[8][2];
#pragma unroll
            for (int ni = 0; ni < 8; ni++) {
                const int n = wn + ni * 8;
                bf[ni][0] = Ws2[buf][k2 + q    ][n + g];
                bf[ni][1] = Ws2[buf][k2 + q + 4][n + g];
            }
#pragma unroll
            for (int mi = 0; mi < 4; mi++)
#pragma unroll
                for (int ni = 0; ni < 8; ni++)
                    mma_f16(acc[mi][ni][0], acc[mi][ni][1], acc[mi][ni][2], acc[mi][ni][3],
                            af[mi][0], af[mi][1], af[mi][2], af[mi][3],
                            bf[ni][0], bf[ni][1]);
        }

        if (more) {
            const int nb = buf ^ 1;
#pragma unroll
            for (int i = 0; i < 4; i++) {
                As2[nb][lkA2 + 2 * i    ][lmA] = pack_h2(av[i].x, av[i].y);
                As2[nb][lkA2 + 2 * i + 1][lmA] = pack_h2(av[i].z, av[i].w);
            }
#pragma unroll
            for (int i = 0; i < 8; i++) {
                Ws2[nb][2 * i    ][tid] = pack_h2(wv[i].x, wv[i].y);
                Ws2[nb][2 * i + 1][tid] = pack_h2(wv[i].z, wv[i].w);
            }
            __syncthreads();
            buf = nb;
        }
    }

#pragma unroll
    for (int mi = 0; mi < 4; mi++) {
#pragma unroll
        for (int ni = 0; ni < 8; ni++) {
            const int m = bm + wm + mi * 16 + g;
            const int n = bn + wn + ni * 8 + 2 * q;
            *(float2*)&Cmat[(size_t)m * N + n] =
                make_float2(acc[mi][ni][0], acc[mi][ni][1]);
            *(float2*)&Cmat[(size_t)(m + 8) * N + n] =
                make_float2(acc[mi][ni][2], acc[mi][ni][3]);
        }
    }
}

// =====================================================================
// Flash attention (causal), fp16 mma m16n8k16 (unchanged from R8 pass).
// =====================================================================
__global__ void __launch_bounds__(128) attn_h(const float* __restrict__ Q,
                                              const float* __restrict__ K,
                                              const float* __restrict__ V,
                                              float* __restrict__ Oatt) {
    __shared__ unsigned Ks2[64][36];
    __shared__ unsigned Vs2[32][72];

    const int tid  = threadIdx.x;
    const int warp = tid >> 5;
    const int lane = tid & 31;
    const int g    = lane >> 2;
    const int q    = lane & 3;
    const int qt   = (int)gridDim.x - 1 - (int)blockIdx.x;
    const int q0   = qt * 64;
    const int bh   = blockIdx.y;
    const int row0 = q0 + warp * 16 + g;
    const int row1 = row0 + 8;

    unsigned Qa[4][4];
    {
        const float* q0p = Q + ((size_t)bh * TT + row0) * HD;
        const float* q1p = Q + ((size_t)bh * TT + row1) * HD;
#pragma unroll
        for (int kc = 0; kc < 4; kc++) {
            int d0 = 16 * kc + 2 * q;
            Qa[kc][0] = pack_h2(0.125f * q0p[d0],     0.125f * q0p[d0 + 1]);
            Qa[kc][1] = pack_h2(0.125f * q1p[d0],     0.125f * q1p[d0 + 1]);
            Qa[kc][2] = pack_h2(0.125f * q0p[d0 + 8], 0.125f * q0p[d0 + 9]);
            Qa[kc][3] = pack_h2(0.125f * q1p[d0 + 8], 0.125f * q1p[d0 + 9]);
        }
    }

    float Oac[8][4];
#pragma unroll
    for (int j = 0; j < 8; j++)
#pragma unroll
        for (int i = 0; i < 4; i++) Oac[j][i] = 0.f;
    float m0_ = -1e30f, m1_ = -1e30f, l0_ = 0.f, l1_ = 0.f;

    const int nkt = qt + 1;
    for (int kt = 0; kt < nkt; kt++) {
        const int k0 = kt * 64;
        __syncthreads();
        {
            const float* kb = K + ((size_t)bh * TT + k0) * HD;
            const float* vb = V + ((size_t)bh * TT + k0) * HD;
            __half* Vsh = (__half*)Vs2;
#pragma unroll
            for (int i = 0; i < 8; i++) {
                int idx4 = tid + i * 128;
                int key = idx4 >> 4, c4 = idx4 & 15;
                int d = 4 * c4;
                float4 a = *(const float4*)(kb + (size_t)key * HD + d);
                float4 b = *(const float4*)(vb + (size_t)key * HD + d);
                uint2 kk2 = make_uint2(pack_h2(a.x, a.y), pack_h2(a.z, a.w));
                *(uint2*)&Ks2[key][2 * c4] = kk2;
                __half* vp = Vsh + (key >> 1) * 144 + 2 * d + (key & 1);
                vp[0] = __float2half_rn(b.x);
                vp[2] = __float2half_rn(b.y);
                vp[4] = __float2half_rn(b.z);
                vp[6] = __float2half_rn(b.w);
            }
        }
        __syncthreads();

        float S[8][4];
#pragma unroll
        for (int j = 0; j < 8; j++)
#pragma unroll
            for (int i = 0; i < 4; i++) S[j][i] = 0.f;

#pragma unroll
        for (int kc = 0; kc < 4; kc++) {
#pragma unroll
            for (int j = 0; j < 8; j++) {
                unsigned b0 = Ks2[8 * j + g][8 * kc + q];
                unsigned b1 = Ks2[8 * j + g][8 * kc + q + 4];
                mma_f16(S[j][0], S[j][1], S[j][2], S[j][3],
                        Qa[kc][0], Qa[kc][1], Qa[kc][2], Qa[kc][3], b0, b1);
            }
        }

        if (kt == nkt - 1) {
#pragma unroll
            for (int j = 0; j < 8; j++) {
                int c = k0 + 8 * j + 2 * q;
                if (c     > row0) S[j][0] = -1e30f;
                if (c + 1 > row0) S[j][1] = -1e30f;
                if (c     > row1) S[j][2] = -1e30f;
                if (c + 1 > row1) S[j][3] = -1e30f;
            }
        }

        float tm0 = -1e30f, tm1 = -1e30f;
#pragma unroll
        for (int j = 0; j < 8; j++) {
            tm0 = fmaxf(tm0, fmaxf(S[j][0], S[j][1]));
            tm1 = fmaxf(tm1, fmaxf(S[j][2], S[j][3]));
        }
        tm0 = fmaxf(tm0, __shfl_xor_sync(0xffffffffu, tm0, 1));
        tm0 = fmaxf(tm0, __shfl_xor_sync(0xffffffffu, tm0, 2));
        tm1 = fmaxf(tm1, __shfl_xor_sync(0xffffffffu, tm1, 1));
        tm1 = fmaxf(tm1, __shfl_xor_sync(0xffffffffu, tm1, 2));

        float nm0 = fmaxf(m0_, tm0), nm1 = fmaxf(m1_, tm1);
        float r0 = __expf(m0_ - nm0), r1 = __expf(m1_ - nm1);
        m0_ = nm0; m1_ = nm1;

        float rs0 = 0.f, rs1 = 0.f;
#pragma unroll
        for (int j = 0; j < 8; j++) {
            S[j][0] = __expf(S[j][0] - nm0);
            S[j][1] = __expf(S[j][1] - nm0);
            S[j][2] = __expf(S[j][2] - nm1);
            S[j][3] = __expf(S[j][3] - nm1);
            rs0 += S[j][0] + S[j][1];
            rs1 += S[j][2] + S[j][3];
        }
        rs0 += __shfl_xor_sync(0xffffffffu, rs0, 1);
        rs0 += __shfl_xor_sync(0xffffffffu, rs0, 2);
        rs1 += __shfl_xor_sync(0xffffffffu, rs1, 1);
        rs1 += __shfl_xor_sync(0xffffffffu, rs1, 2);
        l0_ = l0_ * r0 + rs0;
        l1_ = l1_ * r1 + rs1;

#pragma unroll
        for (int j = 0; j < 8; j++) {
            Oac[j][0] *= r0; Oac[j][1] *= r0;
            Oac[j][2] *= r1; Oac[j][3] *= r1;
        }

#pragma unroll
        for (int kc = 0; kc < 4; kc++) {
            unsigned a0 = pack_h2(S[2 * kc][0],     S[2 * kc][1]);
            unsigned a1 = pack_h2(S[2 * kc][2],     S[2 * kc][3]);
            unsigned a2 = pack_h2(S[2 * kc + 1][0], S[2 * kc + 1][1]);
            unsigned a3 = pack_h2(S[2 * kc + 1][2], S[2 * kc + 1][3]);
#pragma unroll
            for (int j = 0; j < 8; j++) {
                unsigned b0 = Vs2[8 * kc + q][8 * j + g];
                unsigned b1 = Vs2[8 * kc + q + 4][8 * j + g];
                mma_f16(Oac[j][0], Oac[j][1], Oac[j][2], Oac[j][3],
                        a0, a1, a2, a3, b0, b1);
            }
        }
    }

    const int b = bh >> 3, h = bh & 7;
    float inv0 = 1.f / l0_, inv1 = 1.f / l1_;
    float* o0 = Oatt + ((size_t)(b * TT) + row0) * CC + h * HD;
    float* o1 = Oatt + ((size_t)(b * TT) + row1) * CC + h * HD;
#pragma unroll
    for (int j = 0; j < 8; j++) {
        float2 v0 = make_float2(Oac[j][0] * inv0, Oac[j][1] * inv0);
        float2 v1 = make_float2(Oac[j][2] * inv1, Oac[j][3] * inv1);
        *(float2*)&o0[8 * j + 2 * q] = v0;
        *(float2*)&o1[8 * j + 2 * q] = v1;
    }
}

// =====================================================================
extern "C" void kernel_launch(void* const* d_in, const int* in_sizes, int n_in,
                              void* d_out, int out_size) {
    const float* x    = (const float*)d_in[0];
    const float* cosp = (const float*)d_in[1];
    const float* sinp = (const float*)d_in[2];
    const float* Wqkv = (const float*)d_in[3];
    const float* Wout = (const float*)d_in[4];
    float* out = (float*)d_out;

    float *q, *k, *v, *att;
    cudaGetSymbolAddress((void**)&q,   g_q);
    cudaGetSymbolAddress((void**)&k,   g_k);
    cudaGetSymbolAddress((void**)&v,   g_v);
    cudaGetSymbolAddress((void**)&att, g_att);

    // 1) fused: qkv GEMM + RoPE + head-split scatter
    gemm_qkv_rope<<<dim3((3 * CC) / 256, MM / 128), 256>>>(x, Wqkv, cosp, sinp, q, k, v);
    // 2) causal flash attention (fp16 TC)
    attn_h<<<dim3(TT / 64, BH), 128>>>(q, k, v, att);
    // 3) out = att @ Wout^T          (fp16 TC)
    gemm_h_nt<<<dim3(CC / 256, MM / 128), 256>>>(att, Wout, out, MM, CC, CC);
}

// round 10
// speedup vs baseline: 2.2479x; 1.4531x over previous
#include <cuda_runtime.h>
#include <cuda_fp16.h>
#include <cstdint>
#include <math.h>

// Problem constants
#define BB 4
#define TT 2048
#define CC 512
#define HH 8
#define HD 64
#define MM (BB*TT)          // 8192
#define BH (BB*HH)          // 32

// ---------------- device scratch (fp16) ----------------
__device__ __half g_xh[MM * CC];
__device__ __half g_wqkvh[3 * CC * CC];
__device__ __half g_wouth[CC * CC];
__device__ __half g_qh[BH * TT * HD];
__device__ __half g_kh[BH * TT * HD];
__device__ __half g_vh[BH * TT * HD];
__device__ __half g_atth[MM * CC];

// ---------------- helpers ----------------
__device__ __forceinline__ unsigned pack_h2(float x, float y) {
    __half2 h = __floats2half2_rn(x, y);
    return *(unsigned*)&h;
}

__device__ __forceinline__ void mma_f16(float& c0, float& c1, float& c2, float& c3,
                                        unsigned a0, unsigned a1, unsigned a2, unsigned a3,
                                        unsigned b0, unsigned b1) {
    asm volatile(
        "mma.sync.aligned.m16n8k16.row.col.f32.f16.f16.f32 "
        "{%0,%1,%2,%3}, {%4,%5,%6,%7}, {%8,%9}, {%0,%1,%2,%3};"
        : "+f"(c0), "+f"(c1), "+f"(c2), "+f"(c3)
        : "r"(a0), "r"(a1), "r"(a2), "r"(a3), "r"(b0), "r"(b1));
}

__device__ __forceinline__ void ldsm_x4(unsigned& r0, unsigned& r1, unsigned& r2, unsigned& r3,
                                        uint32_t addr) {
    asm volatile("ldmatrix.sync.aligned.m8n8.x4.shared.b16 {%0,%1,%2,%3}, [%4];"
                 : "=r"(r0), "=r"(r1), "=r"(r2), "=r"(r3) : "r"(addr));
}

#define CP_ASYNC16(dst, src) \
    asm volatile("cp.async.cg.shared.global [%0], [%1], 16;" :: "r"(dst), "l"(src))
#define CP_COMMIT() asm volatile("cp.async.commit_group;" ::: "memory")
#define CP_WAIT0()  asm volatile("cp.async.wait_group 0;" ::: "memory")

// swizzled byte offset: pair-packed rows (two m-rows per 128B), chunk c in 0..3
__device__ __forceinline__ uint32_t swz(int row, int c) {
    return (uint32_t)(((row >> 1) * 128) +
                      (((((row & 1) << 2) | c) ^ ((row >> 1) & 7)) << 4));
}

// ---------------- fp32 -> fp16 convert ----------------
__global__ void __launch_bounds__(256) f2h(const float* __restrict__ s,
                                           __half* __restrict__ d, int n) {
    int i = (blockIdx.x * blockDim.x + threadIdx.x) * 4;
    if (i < n) {
        float4 v = *(const float4*)(s + i);
        *(uint2*)(d + i) = make_uint2(pack_h2(v.x, v.y), pack_h2(v.z, v.w));
    }
}

// =====================================================================
// GEMM mainloop (shared by both GEMMs): fp16 A[M,512] @ W[N,512]^T.
// Block 128x256, 8 warps 2x4, warp 64x64, BK=32, cp.async 2-stage,
// ldmatrix.x4 fragments from swizzled smem. 48KB static smem.
// =====================================================================
#define GEMM_MAINLOOP(Aptr, Wptr)                                              \
    __shared__ __align__(16) char sm[49152];                                   \
    const int tid = threadIdx.x, warp = tid >> 5, lane = tid & 31;             \
    const int g = lane >> 2, q = lane & 3;                                     \
    const int jj = lane >> 3, rr = lane & 7;                                   \
    const int bm = blockIdx.y * 128, bn = blockIdx.x * 256;                    \
    const int wm = (warp & 1) * 64, wn = (warp >> 1) * 64;                     \
    const uint32_t smA0 = (uint32_t)__cvta_generic_to_shared(sm);              \
    const uint32_t smB0 = smA0 + 8192;                                         \
    float acc[4][8][4];                                                        \
    _Pragma("unroll") for (int mi = 0; mi < 4; mi++)                           \
    _Pragma("unroll") for (int ni = 0; ni < 8; ni++)                           \
    _Pragma("unroll") for (int c = 0; c < 4; c++) acc[mi][ni][c] = 0.f;        \
    auto load_stage = [&](int s, int koff) {                                   \
        _Pragma("unroll")                                                      \
        for (int i = 0; i < 2; i++) {                                          \
            int idx = tid + i * 256;                                           \
            int m = idx >> 2, c = idx & 3;                                     \
            CP_ASYNC16(smA0 + s * 24576 + swz(m, c),                           \
                       (Aptr) + (size_t)(bm + m) * CC + koff + c * 8);         \
        }                                                                      \
        _Pragma("unroll")                                                      \
        for (int i = 0; i < 4; i++) {                                          \
            int idx = tid + i * 256;                                           \
            int n = idx >> 2, c = idx & 3;                                     \
            CP_ASYNC16(smB0 + s * 24576 + swz(n, c),                           \
                       (Wptr) + (size_t)(bn + n) * CC + koff + c * 8);         \
        }                                                                      \
    };                                                                         \
    load_stage(0, 0);                                                          \
    CP_COMMIT();                                                               \
    CP_WAIT0();                                                                \
    __syncthreads();                                                           \
    int buf = 0;                                                               \
    for (int it = 0; it < 16; it++) {                                          \
        if (it < 15) { load_stage(buf ^ 1, (it + 1) * 32); CP_COMMIT(); }      \
        const uint32_t bA = smA0 + buf * 24576;                                \
        const uint32_t bB = smB0 + buf * 24576;                                \
        _Pragma("unroll")                                                      \
        for (int kc = 0; kc < 2; kc++) {                                       \
            const int cc = 2 * kc + (jj >> 1);                                 \
            unsigned af[4][4];                                                 \
            _Pragma("unroll")                                                  \
            for (int mi = 0; mi < 4; mi++) {                                   \
                int m = wm + mi * 16 + (jj & 1) * 8 + rr;                      \
                ldsm_x4(af[mi][0], af[mi][1], af[mi][2], af[mi][3],            \
                        bA + swz(m, cc));                                      \
            }                                                                  \
            unsigned bf[8][2];                                                 \
            _Pragma("unroll")                                                  \
            for (int nb = 0; nb < 4; nb++) {                                   \
                int n = wn + nb * 16 + (jj & 1) * 8 + rr;                      \
                unsigned t0, t1, t2, t3;                                       \
                ldsm_x4(t0, t1, t2, t3, bB + swz(n, cc));                      \
                bf[2 * nb][0] = t0; bf[2 * nb + 1][0] = t1;                    \
                bf[2 * nb][1] = t2; bf[2 * nb + 1][1] = t3;                    \
            }                                                                  \
            _Pragma("unroll")                                                  \
            for (int mi = 0; mi < 4; mi++)                                     \
            _Pragma("unroll")                                                  \
            for (int ni = 0; ni < 8; ni++)                                     \
                mma_f16(acc[mi][ni][0], acc[mi][ni][1],                        \
                        acc[mi][ni][2], acc[mi][ni][3],                        \
                        af[mi][0], af[mi][1], af[mi][2], af[mi][3],            \
                        bf[ni][0], bf[ni][1]);                                 \
        }                                                                      \
        if (it < 15) { CP_WAIT0(); __syncthreads(); buf ^= 1; }                \
    }

// ---- QKV GEMM + fused RoPE + head split (fp16 out) ----
__global__ void __launch_bounds__(256, 1) gemm_qkv_rope_h(
    const __half* __restrict__ A, const __half* __restrict__ W,
    const float* __restrict__ cosp, const float* __restrict__ sinp,
    __half* __restrict__ qo, __half* __restrict__ ko, __half* __restrict__ vo) {
    GEMM_MAINLOOP(A, W)

    const int n0   = bn + wn;          // head-aligned warp column span
    const int type = n0 >> 9;          // 0=q, 1=k, 2=v
    const int h    = (n0 >> 6) & 7;
    __half* outp = (type == 0) ? qo : (type == 1) ? ko : vo;
    const float sc = (type == 0) ? 0.125f : 1.f;

#pragma unroll
    for (int mi = 0; mi < 4; mi++) {
        const int m  = bm + wm + mi * 16 + g;
        const int b  = m >> 11;
        const int t0 = m & (TT - 1);
        const size_t base0 = ((size_t)(b * HH + h) * TT + t0) * HD;
        const size_t base1 = base0 + 8 * HD;

        if (type == 2) {
#pragma unroll
            for (int ni = 0; ni < 8; ni++) {
                const int d = ni * 8 + 2 * q;
                *(unsigned*)&outp[base0 + d] = pack_h2(acc[mi][ni][0], acc[mi][ni][1]);
                *(unsigned*)&outp[base1 + d] = pack_h2(acc[mi][ni][2], acc[mi][ni][3]);
            }
        } else {
#pragma unroll
            for (int ni = 0; ni < 4; ni++) {
                const int d  = ni * 8 + 2 * q;
                const int du = d + 32;
                float2 cl0 = *(const float2*)&cosp[t0 * HD + d];
                float2 sl0 = *(const float2*)&sinp[t0 * HD + d];
                float2 cu0 = *(const float2*)&cosp[t0 * HD + du];
                float2 su0 = *(const float2*)&sinp[t0 * HD + du];
                float2 cl1 = *(const float2*)&cosp[(t0 + 8) * HD + d];
                float2 sl1 = *(const float2*)&sinp[(t0 + 8) * HD + d];
                float2 cu1 = *(const float2*)&cosp[(t0 + 8) * HD + du];
                float2 su1 = *(const float2*)&sinp[(t0 + 8) * HD + du];

                float x1a = acc[mi][ni][0],     x1b = acc[mi][ni][1];
                float x2a = acc[mi][ni + 4][0], x2b = acc[mi][ni + 4][1];
                *(unsigned*)&outp[base0 + d]  = pack_h2((x1a * cl0.x - x2a * sl0.x) * sc,
                                                        (x1b * cl0.y - x2b * sl0.y) * sc);
                *(unsigned*)&outp[base0 + du] = pack_h2((x2a * cu0.x + x1a * su0.x) * sc,
                                                        (x2b * cu0.y + x1b * su0.y) * sc);
                float y1a = acc[mi][ni][2],     y1b = acc[mi][ni][3];
                float y2a = acc[mi][ni + 4][2], y2b = acc[mi][ni + 4][3];
                *(unsigned*)&outp[base1 + d]  = pack_h2((y1a * cl1.x - y2a * sl1.x) * sc,
                                                        (y1b * cl1.y - y2b * sl1.y) * sc);
                *(unsigned*)&outp[base1 + du] = pack_h2((y2a * cu1.x + y1a * su1.x) * sc,
                                                        (y2b * cu1.y + y1b * su1.y) * sc);
            }
        }
    }
}

// ---- Output projection GEMM (fp16 in, fp32 out) ----
__global__ void __launch_bounds__(256, 1) gemm_out_h(
    const __half* __restrict__ A, const __half* __restrict__ W,
    float* __restrict__ Cmat) {
    GEMM_MAINLOOP(A, W)

#pragma unroll
    for (int mi = 0; mi < 4; mi++) {
#pragma unroll
        for (int ni = 0; ni < 8; ni++) {
            const int m = bm + wm + mi * 16 + g;
            const int n = bn + wn + ni * 8 + 2 * q;
            *(float2*)&Cmat[(size_t)m * CC + n] =
                make_float2(acc[mi][ni][0], acc[mi][ni][1]);
            *(float2*)&Cmat[(size_t)(m + 8) * CC + n] =
                make_float2(acc[mi][ni][2], acc[mi][ni][3]);
        }
    }
}

// =====================================================================
// Flash attention (causal), fp16 in/out, mma m16n8k16.
// q is pre-scaled by 1/8 in the QKV epilogue.
// =====================================================================
__global__ void __launch_bounds__(128) attn_h(const __half* __restrict__ Q,
                                              const __half* __restrict__ K,
                                              const __half* __restrict__ V,
                                              __half* __restrict__ Oatt) {
    __shared__ unsigned Ks2[64][36];   // half2 {d, d+1} per key
    __shared__ unsigned Vs2[32][72];   // half2 {key even, key odd} per d

    const int tid  = threadIdx.x;
    const int warp = tid >> 5;
    const int lane = tid & 31;
    const int g    = lane >> 2;
    const int q    = lane & 3;
    const int qt   = (int)gridDim.x - 1 - (int)blockIdx.x;
    const int q0   = qt * 64;
    const int bh   = blockIdx.y;
    const int row0 = q0 + warp * 16 + g;
    const int row1 = row0 + 8;

    unsigned Qa[4][4];
    {
        const __half* q0p = Q + ((size_t)bh * TT + row0) * HD;
        const __half* q1p = Q + ((size_t)bh * TT + row1) * HD;
#pragma unroll
        for (int kc = 0; kc < 4; kc++) {
            int d0 = 16 * kc + 2 * q;
            Qa[kc][0] = *(const unsigned*)(q0p + d0);
            Qa[kc][1] = *(const unsigned*)(q1p + d0);
            Qa[kc][2] = *(const unsigned*)(q0p + d0 + 8);
            Qa[kc][3] = *(const unsigned*)(q1p + d0 + 8);
        }
    }

    float Oac[8][4];
#pragma unroll
    for (int j = 0; j < 8; j++)
#pragma unroll
        for (int i = 0; i < 4; i++) Oac[j][i] = 0.f;
    float m0_ = -1e30f, m1_ = -1e30f, l0_ = 0.f, l1_ = 0.f;

    const int nkt = qt + 1;
    for (int kt = 0; kt < nkt; kt++) {
        const int k0 = kt * 64;
        __syncthreads();
        {
            const __half* kb = K + ((size_t)bh * TT + k0) * HD;
            const __half* vb = V + ((size_t)bh * TT + k0) * HD;
            __half* Vsh = (__half*)Vs2;
            // K: direct 16B copies
#pragma unroll
            for (int i = 0; i < 4; i++) {
                int idx = tid + i * 128;            // 0..511
                int key = idx >> 3, c8 = idx & 7;
                *(uint4*)&Ks2[key][4 * c8] =
                    *(const uint4*)(kb + (size_t)key * HD + 8 * c8);
            }
            // V: scatter into key-pair-packed layout
#pragma unroll
            for (int i = 0; i < 8; i++) {
                int idx4 = tid + i * 128;           // 0..1023
                int key = idx4 >> 4, c4 = idx4 & 15;
                int d = 4 * c4;
                uint2 hv = *(const uint2*)(vb + (size_t)key * HD + d);
                __half2 p0 = *(__half2*)&hv.x;
                __half2 p1 = *(__half2*)&hv.y;
                __half* vp = Vsh + (key >> 1) * 144 + 2 * d + (key & 1);
                vp[0] = p0.x; vp[2] = p0.y; vp[4] = p1.x; vp[6] = p1.y;
            }
        }
        __syncthreads();

        float S[8][4];
#pragma unroll
        for (int j = 0; j < 8; j++)
#pragma unroll
            for (int i = 0; i < 4; i++) S[j][i] = 0.f;

#pragma unroll
        for (int kc = 0; kc < 4; kc++) {
#pragma unroll
            for (int j = 0; j < 8; j++) {
                unsigned b0 = Ks2[8 * j + g][8 * kc + q];
                unsigned b1 = Ks2[8 * j + g][8 * kc + q + 4];
                mma_f16(S[j][0], S[j][1], S[j][2], S[j][3],
                        Qa[kc][0], Qa[kc][1], Qa[kc][2], Qa[kc][3], b0, b1);
            }
        }

        if (kt == nkt - 1) {
#pragma unroll
            for (int j = 0; j < 8; j++) {
                int c = k0 + 8 * j + 2 * q;
                if (c     > row0) S[j][0] = -1e30f;
                if (c + 1 > row0) S[j][1] = -1e30f;
                if (c     > row1) S[j][2] = -1e30f;
                if (c + 1 > row1) S[j][3] = -1e30f;
            }
        }

        float tm0 = -1e30f, tm1 = -1e30f;
#pragma unroll
        for (int j = 0; j < 8; j++) {
            tm0 = fmaxf(tm0, fmaxf(S[j][0], S[j][1]));
            tm1 = fmaxf(tm1, fmaxf(S[j][2], S[j][3]));
        }
        tm0 = fmaxf(tm0, __shfl_xor_sync(0xffffffffu, tm0, 1));
        tm0 = fmaxf(tm0, __shfl_xor_sync(0xffffffffu, tm0, 2));
        tm1 = fmaxf(tm1, __shfl_xor_sync(0xffffffffu, tm1, 1));
        tm1 = fmaxf(tm1, __shfl_xor_sync(0xffffffffu, tm1, 2));

        float nm0 = fmaxf(m0_, tm0), nm1 = fmaxf(m1_, tm1);
        float r0 = __expf(m0_ - nm0), r1 = __expf(m1_ - nm1);
        m0_ = nm0; m1_ = nm1;

        float rs0 = 0.f, rs1 = 0.f;
#pragma unroll
        for (int j = 0; j < 8; j++) {
            S[j][0] = __expf(S[j][0] - nm0);
            S[j][1] = __expf(S[j][1] - nm0);
            S[j][2] = __expf(S[j][2] - nm1);
            S[j][3] = __expf(S[j][3] - nm1);
            rs0 += S[j][0] + S[j][1];
            rs1 += S[j][2] + S[j][3];
        }
        rs0 += __shfl_xor_sync(0xffffffffu, rs0, 1);
        rs0 += __shfl_xor_sync(0xffffffffu, rs0, 2);
        rs1 += __shfl_xor_sync(0xffffffffu, rs1, 1);
        rs1 += __shfl_xor_sync(0xffffffffu, rs1, 2);
        l0_ = l0_ * r0 + rs0;
        l1_ = l1_ * r1 + rs1;

#pragma unroll
        for (int j = 0; j < 8; j++) {
            Oac[j][0] *= r0; Oac[j][1] *= r0;
            Oac[j][2] *= r1; Oac[j][3] *= r1;
        }

#pragma unroll
        for (int kc = 0; kc < 4; kc++) {
            unsigned a0 = pack_h2(S[2 * kc][0],     S[2 * kc][1]);
            unsigned a1 = pack_h2(S[2 * kc][2],     S[2 * kc][3]);
            unsigned a2 = pack_h2(S[2 * kc + 1][0], S[2 * kc + 1][1]);
            unsigned a3 = pack_h2(S[2 * kc + 1][2], S[2 * kc + 1][3]);
#pragma unroll
            for (int j = 0; j < 8; j++) {
                unsigned b0 = Vs2[8 * kc + q][8 * j + g];
                unsigned b1 = Vs2[8 * kc + q + 4][8 * j + g];
                mma_f16(Oac[j][0], Oac[j][1], Oac[j][2], Oac[j][3],
                        a0, a1, a2, a3, b0, b1);
            }
        }
    }

    const int b = bh >> 3, h = bh & 7;
    float inv0 = 1.f / l0_, inv1 = 1.f / l1_;
    __half* o0 = Oatt + ((size_t)(b * TT) + row0) * CC + h * HD;
    __half* o1 = Oatt + ((size_t)(b * TT) + row1) * CC + h * HD;
#pragma unroll
    for (int j = 0; j < 8; j++) {
        *(unsigned*)&o0[8 * j + 2 * q] = pack_h2(Oac[j][0] * inv0, Oac[j][1] * inv0);
        *(unsigned*)&o1[8 * j + 2 * q] = pack_h2(Oac[j][2] * inv1, Oac[j][3] * inv1);
    }
}

// =====================================================================
extern "C" void kernel_launch(void* const* d_in, const int* in_sizes, int n_in,
                              void* d_out, int out_size) {
    const float* x    = (const float*)d_in[0];
    const float* cosp = (const float*)d_in[1];
    const float* sinp = (const float*)d_in[2];
    const float* Wqkv = (const float*)d_in[3];
    const float* Wout = (const float*)d_in[4];
    float* out = (float*)d_out;

    __half *xh, *wqkvh, *wouth, *qh, *kh, *vh, *atth;
    cudaGetSymbolAddress((void**)&xh,    g_xh);
    cudaGetSymbolAddress((void**)&wqkvh, g_wqkvh);
    cudaGetSymbolAddress((void**)&wouth, g_wouth);
    cudaGetSymbolAddress((void**)&qh,    g_qh);
    cudaGetSymbolAddress((void**)&kh,    g_kh);
    cudaGetSymbolAddress((void**)&vh,    g_vh);
    cudaGetSymbolAddress((void**)&atth,  g_atth);

    // 0) fp32 -> fp16 input conversion (same rounding the GEMMs did before)
    f2h<<<(MM * CC) / 4 / 256, 256>>>(x, xh, MM * CC);
    f2h<<<(3 * CC * CC) / 4 / 256, 256>>>(Wqkv, wqkvh, 3 * CC * CC);
    f2h<<<(CC * CC) / 4 / 256, 256>>>(Wout, wouth, CC * CC);

    // 1) fused QKV GEMM + RoPE + head-split (fp16 out, q pre-scaled)
    gemm_qkv_rope_h<<<dim3((3 * CC) / 256, MM / 128), 256>>>(
        xh, wqkvh, cosp, sinp, qh, kh, vh);
    // 2) causal flash attention (fp16 in/out)
    attn_h<<<dim3(TT / 64, BH), 128>>>(qh, kh, vh, atth);
    // 3) out = att @ Wout^T (fp16 in, fp32 out)
    gemm_out_h<<<dim3(CC / 256, MM / 128), 256>>>(atth, wouth, out);
}

// round 11
// speedup vs baseline: 2.5068x; 1.1152x over previous
#include <cuda_runtime.h>
#include <cuda_fp16.h>
#include <cstdint>
#include <math.h>

// Problem constants
#define BB 4
#define TT 2048
#define CC 512
#define HH 8
#define HD 64
#define MM (BB*TT)          // 8192
#define BH (BB*HH)          // 32

// ---------------- device scratch (fp16) ----------------
__device__ __half g_xh[MM * CC];
__device__ __half g_wqkvh[3 * CC * CC];
__device__ __half g_wouth[CC * CC];
__device__ __half g_qh[BH * TT * HD];
__device__ __half g_kh[BH * TT * HD];
__device__ __half g_vh[BH * TT * HD];
__device__ __half g_atth[MM * CC];

// ---------------- helpers ----------------
__device__ __forceinline__ unsigned pack_h2(float x, float y) {
    __half2 h = __floats2half2_rn(x, y);
    return *(unsigned*)&h;
}

__device__ __forceinline__ void mma_f16(float& c0, float& c1, float& c2, float& c3,
                                        unsigned a0, unsigned a1, unsigned a2, unsigned a3,
                                        unsigned b0, unsigned b1) {
    asm volatile(
        "mma.sync.aligned.m16n8k16.row.col.f32.f16.f16.f32 "
        "{%0,%1,%2,%3}, {%4,%5,%6,%7}, {%8,%9}, {%0,%1,%2,%3};"
        : "+f"(c0), "+f"(c1), "+f"(c2), "+f"(c3)
        : "r"(a0), "r"(a1), "r"(a2), "r"(a3), "r"(b0), "r"(b1));
}

__device__ __forceinline__ void ldsm_x4(unsigned& r0, unsigned& r1, unsigned& r2, unsigned& r3,
                                        uint32_t addr) {
    asm volatile("ldmatrix.sync.aligned.m8n8.x4.shared.b16 {%0,%1,%2,%3}, [%4];"
                 : "=r"(r0), "=r"(r1), "=r"(r2), "=r"(r3) : "r"(addr));
}

#define CP_ASYNC16(dst, src) \
    asm volatile("cp.async.cg.shared.global [%0], [%1], 16;" :: "r"(dst), "l"(src))
#define CP_COMMIT() asm volatile("cp.async.commit_group;" ::: "memory")
#define CP_WAIT0()  asm volatile("cp.async.wait_group 0;" ::: "memory")

// swizzled byte offset: pair-packed rows (two rows per 128B), chunk c in 0..3
__device__ __forceinline__ uint32_t swz(int row, int c) {
    return (uint32_t)(((row >> 1) * 128) +
                      (((((row & 1) << 2) | c) ^ ((row >> 1) & 7)) << 4));
}

// ---------------- fp32 -> fp16 convert (all three tensors, one launch) ----
__global__ void __launch_bounds__(256) f2h3(const float* __restrict__ a, __half* __restrict__ da, int na,
                                            const float* __restrict__ b, __half* __restrict__ db, int nb,
                                            const float* __restrict__ c, __half* __restrict__ dc, int nc) {
    int t = (blockIdx.x * blockDim.x + threadIdx.x) * 4;
    const float* s; __half* d; int i;
    if (t < na)            { s = a; d = da; i = t; }
    else if (t < na + nb)  { s = b; d = db; i = t - na; }
    else if (t < na + nb + nc) { s = c; d = dc; i = t - na - nb; }
    else return;
    float4 v = *(const float4*)(s + i);
    *(uint2*)(d + i) = make_uint2(pack_h2(v.x, v.y), pack_h2(v.z, v.w));
}

// =====================================================================
// GEMM mainloop: fp16 A[M,512] @ W[N,512]^T. Block 128x128, 8 warps
// of 32(m)x64(n) [4x2], BK=32, cp.async 2-stage, ldmatrix.x4 with
// HOISTED swizzled addresses. 32KB smem, ~110 regs -> 2 CTAs/SM.
// =====================================================================
#define GEMM_MAINLOOP(Aptr, Wptr)                                              \
    __shared__ __align__(16) char sm[32768];                                   \
    const int tid = threadIdx.x, warp = tid >> 5, lane = tid & 31;             \
    const int g = lane >> 2, q = lane & 3;                                     \
    const int jj = lane >> 3, rr = lane & 7;                                   \
    const int bm = blockIdx.y * 128, bn = blockIdx.x * 128;                    \
    const int wm = (warp >> 1) * 32, wn = (warp & 1) * 64;                     \
    const uint32_t smA0 = (uint32_t)__cvta_generic_to_shared(sm);              \
    const uint32_t smB0 = smA0 + 16384;                                        \
    float acc[2][8][4];                                                        \
    _Pragma("unroll") for (int mi = 0; mi < 2; mi++)                           \
    _Pragma("unroll") for (int ni = 0; ni < 8; ni++)                           \
    _Pragma("unroll") for (int cz = 0; cz < 4; cz++) acc[mi][ni][cz] = 0.f;    \
    uint32_t aAdr[2][2], bAdr[4][2];                                           \
    _Pragma("unroll")                                                          \
    for (int mi = 0; mi < 2; mi++)                                             \
    _Pragma("unroll")                                                          \
    for (int kc = 0; kc < 2; kc++) {                                           \
        int m = wm + mi * 16 + (jj & 1) * 8 + rr;                              \
        aAdr[mi][kc] = smA0 + swz(m, 2 * kc + (jj >> 1));                      \
    }                                                                          \
    _Pragma("unroll")                                                          \
    for (int nb = 0; nb < 4; nb++)                                             \
    _Pragma("unroll")                                                          \
    for (int kc = 0; kc < 2; kc++) {                                           \
        int n = wn + nb * 16 + (jj & 1) * 8 + rr;                              \
        bAdr[nb][kc] = smB0 + swz(n, 2 * kc + (jj >> 1));                      \
    }                                                                          \
    auto load_stage = [&](int s, int koff) {                                   \
        _Pragma("unroll")                                                      \
        for (int i = 0; i < 2; i++) {                                          \
            int idx = tid + i * 256;                                           \
            int m = idx >> 2, cch = idx & 3;                                   \
            CP_ASYNC16(smA0 + s * 8192 + swz(m, cch),                          \
                       (Aptr) + (size_t)(bm + m) * CC + koff + cch * 8);       \
        }                                                                      \
        _Pragma("unroll")                                                      \
        for (int i = 0; i < 2; i++) {                                          \
            int idx = tid + i * 256;                                           \
            int n = idx >> 2, cch = idx & 3;                                   \
            CP_ASYNC16(smB0 + s * 8192 + swz(n, cch),                          \
                       (Wptr) + (size_t)(bn + n) * CC + koff + cch * 8);       \
        }                                                                      \
    };                                                                         \
    load_stage(0, 0);                                                          \
    CP_COMMIT();                                                               \
    CP_WAIT0();                                                                \
    __syncthreads();                                                           \
    int buf = 0;                                                               \
    for (int it = 0; it < 16; it++) {                                          \
        if (it < 15) { load_stage(buf ^ 1, (it + 1) * 32); CP_COMMIT(); }      \
        const uint32_t off = buf * 8192;                                       \
        _Pragma("unroll")                                                      \
        for (int kc = 0; kc < 2; kc++) {                                       \
            unsigned af[2][4];                                                 \
            _Pragma("unroll")                                                  \
            for (int mi = 0; mi < 2; mi++)                                     \
                ldsm_x4(af[mi][0], af[mi][1], af[mi][2], af[mi][3],            \
                        aAdr[mi][kc] + off);                                   \
            unsigned bf[8][2];                                                 \
            _Pragma("unroll")                                                  \
            for (int nb = 0; nb < 4; nb++) {                                   \
                unsigned t0, t1, t2, t3;                                       \
                ldsm_x4(t0, t1, t2, t3, bAdr[nb][kc] + off);                   \
                bf[2 * nb][0] = t0; bf[2 * nb + 1][0] = t1;                    \
                bf[2 * nb][1] = t2; bf[2 * nb + 1][1] = t3;                    \
            }                                                                  \
            _Pragma("unroll")                                                  \
            for (int mi = 0; mi < 2; mi++)                                     \
            _Pragma("unroll")                                                  \
            for (int ni = 0; ni < 8; ni++)                                     \
                mma_f16(acc[mi][ni][0], acc[mi][ni][1],                        \
                        acc[mi][ni][2], acc[mi][ni][3],                        \
                        af[mi][0], af[mi][1], af[mi][2], af[mi][3],            \
                        bf[ni][0], bf[ni][1]);                                 \
        }                                                                      \
        if (it < 15) { CP_WAIT0(); __syncthreads(); buf ^= 1; }                \
    }

// ---- QKV GEMM + fused RoPE + head split (fp16 out) ----
__global__ void __launch_bounds__(256, 2) gemm_qkv_rope_h(
    const __half* __restrict__ A, const __half* __restrict__ W,
    const float* __restrict__ cosp, const float* __restrict__ sinp,
    __half* __restrict__ qo, __half* __restrict__ ko, __half* __restrict__ vo) {
    GEMM_MAINLOOP(A, W)

    const int n0   = bn + wn;          // head-aligned 64-wide warp span
    const int type = n0 >> 9;          // 0=q, 1=k, 2=v
    const int h    = (n0 >> 6) & 7;
    __half* outp = (type == 0) ? qo : (type == 1) ? ko : vo;
    const float sc = (type == 0) ? 0.125f : 1.f;

#pragma unroll
    for (int mi = 0; mi < 2; mi++) {
        const int m  = bm + wm + mi * 16 + g;
        const int b  = m >> 11;
        const int t0 = m & (TT - 1);
        const size_t base0 = ((size_t)(b * HH + h) * TT + t0) * HD;
        const size_t base1 = base0 + 8 * HD;

        if (type == 2) {
#pragma unroll
            for (int ni = 0; ni < 8; ni++) {
                const int d = ni * 8 + 2 * q;
                *(unsigned*)&outp[base0 + d] = pack_h2(acc[mi][ni][0], acc[mi][ni][1]);
                *(unsigned*)&outp[base1 + d] = pack_h2(acc[mi][ni][2], acc[mi][ni][3]);
            }
        } else {
#pragma unroll
            for (int ni = 0; ni < 4; ni++) {
                const int d  = ni * 8 + 2 * q;
                const int du = d + 32;
                float2 cl0 = *(const float2*)&cosp[t0 * HD + d];
                float2 sl0 = *(const float2*)&sinp[t0 * HD + d];
                float2 cu0 = *(const float2*)&cosp[t0 * HD + du];
                float2 su0 = *(const float2*)&sinp[t0 * HD + du];
                float2 cl1 = *(const float2*)&cosp[(t0 + 8) * HD + d];
                float2 sl1 = *(const float2*)&sinp[(t0 + 8) * HD + d];
                float2 cu1 = *(const float2*)&cosp[(t0 + 8) * HD + du];
                float2 su1 = *(const float2*)&sinp[(t0 + 8) * HD + du];

                float x1a = acc[mi][ni][0],     x1b = acc[mi][ni][1];
                float x2a = acc[mi][ni + 4][0], x2b = acc[mi][ni + 4][1];
                *(unsigned*)&outp[base0 + d]  = pack_h2((x1a * cl0.x - x2a * sl0.x) * sc,
                                                        (x1b * cl0.y - x2b * sl0.y) * sc);
                *(unsigned*)&outp[base0 + du] = pack_h2((x2a * cu0.x + x1a * su0.x) * sc,
                                                        (x2b * cu0.y + x1b * su0.y) * sc);
                float y1a = acc[mi][ni][2],     y1b = acc[mi][ni][3];
                float y2a = acc[mi][ni + 4][2], y2b = acc[mi][ni + 4][3];
                *(unsigned*)&outp[base1 + d]  = pack_h2((y1a * cl1.x - y2a * sl1.x) * sc,
                                                        (y1b * cl1.y - y2b * sl1.y) * sc);
                *(unsigned*)&outp[base1 + du] = pack_h2((y2a * cu1.x + y1a * su1.x) * sc,
                                                        (y2b * cu1.y + y1b * su1.y) * sc);
            }
        }
    }
}

// ---- Output projection GEMM (fp16 in, fp32 out) ----
__global__ void __launch_bounds__(256, 2) gemm_out_h(
    const __half* __restrict__ A, const __half* __restrict__ W,
    float* __restrict__ Cmat) {
    GEMM_MAINLOOP(A, W)

#pragma unroll
    for (int mi = 0; mi < 2; mi++) {
#pragma unroll
        for (int ni = 0; ni < 8; ni++) {
            const int m = bm + wm + mi * 16 + g;
            const int n = bn + wn + ni * 8 + 2 * q;
            *(float2*)&Cmat[(size_t)m * CC + n] =
                make_float2(acc[mi][ni][0], acc[mi][ni][1]);
            *(float2*)&Cmat[(size_t)(m + 8) * CC + n] =
                make_float2(acc[mi][ni][2], acc[mi][ni][3]);
        }
    }
}

// =====================================================================
// Flash attention (causal), fp16 in/out, mma m16n8k16.
// q-tile 128 rows (8 warps, 256 threads), k-tile 64.
// Diagonal straddles the last TWO ktiles -> mask when kt >= nkt-2.
// =====================================================================
__global__ void __launch_bounds__(256) attn_h(const __half* __restrict__ Q,
                                              const __half* __restrict__ K,
                                              const __half* __restrict__ V,
                                              __half* __restrict__ Oatt) {
    __shared__ unsigned Ks2[64][36];   // half2 {d, d+1} per key
    __shared__ unsigned Vs2[32][72];   // half2 {key even, key odd} per d

    const int tid  = threadIdx.x;
    const int warp = tid >> 5;         // 0..7
    const int lane = tid & 31;
    const int g    = lane >> 2;
    const int q    = lane & 3;
    const int qt   = (int)gridDim.x - 1 - (int)blockIdx.x;   // big tiles first
    const int q0   = qt * 128;
    const int bh   = blockIdx.y;
    const int row0 = q0 + warp * 16 + g;
    const int row1 = row0 + 8;

    unsigned Qa[4][4];
    {
        const __half* q0p = Q + ((size_t)bh * TT + row0) * HD;
        const __half* q1p = Q + ((size_t)bh * TT + row1) * HD;
#pragma unroll
        for (int kc = 0; kc < 4; kc++) {
            int d0 = 16 * kc + 2 * q;
            Qa[kc][0] = *(const unsigned*)(q0p + d0);
            Qa[kc][1] = *(const unsigned*)(q1p + d0);
            Qa[kc][2] = *(const unsigned*)(q0p + d0 + 8);
            Qa[kc][3] = *(const unsigned*)(q1p + d0 + 8);
        }
    }

    float Oac[8][4];
#pragma unroll
    for (int j = 0; j < 8; j++)
#pragma unroll
        for (int i = 0; i < 4; i++) Oac[j][i] = 0.f;
    float m0_ = -1e30f, m1_ = -1e30f, l0_ = 0.f, l1_ = 0.f;

    const int nkt = 2 * qt + 2;
    for (int kt = 0; kt < nkt; kt++) {
        const int k0 = kt * 64;
        __syncthreads();
        {
            const __half* kb = K + ((size_t)bh * TT + k0) * HD;
            const __half* vb = V + ((size_t)bh * TT + k0) * HD;
            __half* Vsh = (__half*)Vs2;
            // K: 512 x 16B over 256 threads
#pragma unroll
            for (int i = 0; i < 2; i++) {
                int idx = tid + i * 256;
                int key = idx >> 3, c8 = idx & 7;
                *(uint4*)&Ks2[key][4 * c8] =
                    *(const uint4*)(kb + (size_t)key * HD + 8 * c8);
            }
            // V: 1024 x 8B over 256 threads, scatter key-pair-packed
#pragma unroll
            for (int i = 0; i < 4; i++) {
                int idx4 = tid + i * 256;
                int key = idx4 >> 4, c4 = idx4 & 15;
                int d = 4 * c4;
                uint2 hv = *(const uint2*)(vb + (size_t)key * HD + d);
                __half2 p0 = *(__half2*)&hv.x;
                __half2 p1 = *(__half2*)&hv.y;
                __half* vp = Vsh + (key >> 1) * 144 + 2 * d + (key & 1);
                vp[0] = p0.x; vp[2] = p0.y; vp[4] = p1.x; vp[6] = p1.y;
            }
        }
        __syncthreads();

        float S[8][4];
#pragma unroll
        for (int j = 0; j < 8; j++)
#pragma unroll
            for (int i = 0; i < 4; i++) S[j][i] = 0.f;

#pragma unroll
        for (int kc = 0; kc < 4; kc++) {
#pragma unroll
            for (int j = 0; j < 8; j++) {
                unsigned b0 = Ks2[8 * j + g][8 * kc + q];
                unsigned b1 = Ks2[8 * j + g][8 * kc + q + 4];
                mma_f16(S[j][0], S[j][1], S[j][2], S[j][3],
                        Qa[kc][0], Qa[kc][1], Qa[kc][2], Qa[kc][3], b0, b1);
            }
        }

        if (kt >= nkt - 2) {
#pragma unroll
            for (int j = 0; j < 8; j++) {
                int c = k0 + 8 * j + 2 * q;
                if (c     > row0) S[j][0] = -1e30f;
                if (c + 1 > row0) S[j][1] = -1e30f;
                if (c     > row1) S[j][2] = -1e30f;
                if (c + 1 > row1) S[j][3] = -1e30f;
            }
        }

        float tm0 = -1e30f, tm1 = -1e30f;
#pragma unroll
        for (int j = 0; j < 8; j++) {
            tm0 = fmaxf(tm0, fmaxf(S[j][0], S[j][1]));
            tm1 = fmaxf(tm1, fmaxf(S[j][2], S[j][3]));
        }
        tm0 = fmaxf(tm0, __shfl_xor_sync(0xffffffffu, tm0, 1));
        tm0 = fmaxf(tm0, __shfl_xor_sync(0xffffffffu, tm0, 2));
        tm1 = fmaxf(tm1, __shfl_xor_sync(0xffffffffu, tm1, 1));
        tm1 = fmaxf(tm1, __shfl_xor_sync(0xffffffffu, tm1, 2));

        float nm0 = fmaxf(m0_, tm0), nm1 = fmaxf(m1_, tm1);
        float r0 = __expf(m0_ - nm0), r1 = __expf(m1_ - nm1);
        m0_ = nm0; m1_ = nm1;

        float rs0 = 0.f, rs1 = 0.f;
#pragma unroll
        for (int j = 0; j < 8; j++) {
            S[j][0] = __expf(S[j][0] - nm0);
            S[j][1] = __expf(S[j][1] - nm0);
            S[j][2] = __expf(S[j][2] - nm1);
            S[j][3] = __expf(S[j][3] - nm1);
            rs0 += S[j][0] + S[j][1];
            rs1 += S[j][2] + S[j][3];
        }
        rs0 += __shfl_xor_sync(0xffffffffu, rs0, 1);
        rs0 += __shfl_xor_sync(0xffffffffu, rs0, 2);
        rs1 += __shfl_xor_sync(0xffffffffu, rs1, 1);
        rs1 += __shfl_xor_sync(0xffffffffu, rs1, 2);
        l0_ = l0_ * r0 + rs0;
        l1_ = l1_ * r1 + rs1;

#pragma unroll
        for (int j = 0; j < 8; j++) {
            Oac[j][0] *= r0; Oac[j][1] *= r0;
            Oac[j][2] *= r1; Oac[j][3] *= r1;
        }

#pragma unroll
        for (int kc = 0; kc < 4; kc++) {
            unsigned a0 = pack_h2(S[2 * kc][0],     S[2 * kc][1]);
            unsigned a1 = pack_h2(S[2 * kc][2],     S[2 * kc][3]);
            unsigned a2 = pack_h2(S[2 * kc + 1][0], S[2 * kc + 1][1]);
            unsigned a3 = pack_h2(S[2 * kc + 1][2], S[2 * kc + 1][3]);
#pragma unroll
            for (int j = 0; j < 8; j++) {
                unsigned b0 = Vs2[8 * kc + q][8 * j + g];
                unsigned b1 = Vs2[8 * kc + q + 4][8 * j + g];
                mma_f16(Oac[j][0], Oac[j][1], Oac[j][2], Oac[j][3],
                        a0, a1, a2, a3, b0, b1);
            }
        }
    }

    const int b = bh >> 3, h = bh & 7;
    float inv0 = 1.f / l0_, inv1 = 1.f / l1_;
    __half* o0 = Oatt + ((size_t)(b * TT) + row0) * CC + h * HD;
    __half* o1 = Oatt + ((size_t)(b * TT) + row1) * CC + h * HD;
#pragma unroll
    for (int j = 0; j < 8; j++) {
        *(unsigned*)&o0[8 * j + 2 * q] = pack_h2(Oac[j][0] * inv0, Oac[j][1] * inv0);
        *(unsigned*)&o1[8 * j + 2 * q] = pack_h2(Oac[j][2] * inv1, Oac[j][3] * inv1);
    }
}

// =====================================================================
extern "C" void kernel_launch(void* const* d_in, const int* in_sizes, int n_in,
                              void* d_out, int out_size) {
    const float* x    = (const float*)d_in[0];
    const float* cosp = (const float*)d_in[1];
    const float* sinp = (const float*)d_in[2];
    const float* Wqkv = (const float*)d_in[3];
    const float* Wout = (const float*)d_in[4];
    float* out = (float*)d_out;

    __half *xh, *wqkvh, *wouth, *qh, *kh, *vh, *atth;
    cudaGetSymbolAddress((void**)&xh,    g_xh);
    cudaGetSymbolAddress((void**)&wqkvh, g_wqkvh);
    cudaGetSymbolAddress((void**)&wouth, g_wouth);
    cudaGetSymbolAddress((void**)&qh,    g_qh);
    cudaGetSymbolAddress((void**)&kh,    g_kh);
    cudaGetSymbolAddress((void**)&vh,    g_vh);
    cudaGetSymbolAddress((void**)&atth,  g_atth);

    const int na = MM * CC, nb = 3 * CC * CC, nc = CC * CC;
    // 0) fp32 -> fp16 conversion (one launch)
    f2h3<<<(na + nb + nc) / 4 / 256, 256>>>(x, xh, na, Wqkv, wqkvh, nb, Wout, wouth, nc);
    // 1) fused QKV GEMM + RoPE + head-split (fp16 out, q pre-scaled)
    gemm_qkv_rope_h<<<dim3((3 * CC) / 128, MM / 128), 256>>>(
        xh, wqkvh, cosp, sinp, qh, kh, vh);
    // 2) causal flash attention (q-tile 128)
    attn_h<<<dim3(TT / 128, BH), 256>>>(qh, kh, vh, atth);
    // 3) out = att @ Wout^T (fp16 in, fp32 out)
    gemm_out_h<<<dim3(CC / 128, MM / 128), 256>>>(atth, wouth, out);
}